// round 1
// baseline (speedup 1.0000x reference)
#include <cuda_runtime.h>

// Problem constants
#define CB   2048   // batch
#define CT   64     // T_enc == T_steps
#define CM   256    // M
#define CP   256    // P
#define G    14     // batches per block
#define GP   16     // padded G (float4-friendly row stride)
#define NBLK 147    // ceil(2048/14)

#define SMEM_FLOATS (4096*4 + 3584*2 + 896 + 16)
#define SMEM_BYTES  (SMEM_FLOATS * 4)

// ---------------- device scratch (no allocation allowed) ----------------
__device__ float g_Ue[(size_t)CB * CT * CM];   // [bt][n]  (128 MB)
__device__ float g_WdT[512 * 256];             // [k][n] = W_d_w[n][k]
__device__ float g_WhhT[256 * 1024];           // [k][j] = W_hh[j][k]
__device__ float g_UdT[256 * 256];             // [m][n] = U_d_w[n][m]
__device__ float g_bcomb[1024];                // b_ih + b_hh
__device__ float g_weff[512];                  // v_y @ W_y  (folded head)
__device__ float g_beff[1];                    // v_y @ W_y_b + v_y_b

// ---------------- fast math helpers ----------------
__device__ __forceinline__ float fast_ex2(float x) {
    float y; asm("ex2.approx.f32 %0, %1;" : "=f"(y) : "f"(x)); return y;
}
__device__ __forceinline__ float fast_rcp(float x) {
    float y; asm("rcp.approx.f32 %0, %1;" : "=f"(y) : "f"(x)); return y;
}
// tanh(x) = 1 - 2/(e^{2x}+1): ~1e-7 accurate, 2 MUFU ops
__device__ __forceinline__ float tanh_f(float x) {
    float e = fast_ex2(2.8853900817779268f * x);
    return fmaf(-2.f, fast_rcp(e + 1.f), 1.f);
}
__device__ __forceinline__ float sigm_f(float x) {
    float e = fast_ex2(-1.4426950408889634f * x);
    return fast_rcp(1.f + e);
}
__device__ __forceinline__ float wredsum(float s) {
#pragma unroll
    for (int o = 16; o; o >>= 1) s += __shfl_xor_sync(0xffffffffu, s, o);
    return s;
}
__device__ __forceinline__ float wredmax(float s) {
#pragma unroll
    for (int o = 16; o; o >>= 1) s = fmaxf(s, __shfl_xor_sync(0xffffffffu, s, o));
    return s;
}

#define LOAD14(dv, ptr) {                                                   \
    const float4* _r = (const float4*)(ptr);                                \
    float4 _a = _r[0], _b = _r[1], _c = _r[2];                              \
    float2 _d = ((const float2*)(ptr))[6];                                  \
    dv[0]=_a.x; dv[1]=_a.y; dv[2]=_a.z; dv[3]=_a.w;                         \
    dv[4]=_b.x; dv[5]=_b.y; dv[6]=_b.z; dv[7]=_b.w;                         \
    dv[8]=_c.x; dv[9]=_c.y; dv[10]=_c.z; dv[11]=_c.w;                       \
    dv[12]=_d.x; dv[13]=_d.y; }

// ---------------- prep: transposes + folded head ----------------
__global__ void prep_kernel(const float* __restrict__ Wd,
                            const float* __restrict__ Whh,
                            const float* __restrict__ Ud,
                            const float* __restrict__ bih,
                            const float* __restrict__ bhh,
                            const float* __restrict__ vy,
                            const float* __restrict__ Wy,
                            const float* __restrict__ Wyb,
                            const float* __restrict__ vyb)
{
    int i = blockIdx.x * blockDim.x + threadIdx.x;
    if (i < 131072) { int k = i >> 8, n = i & 255; g_WdT[i] = Wd[n * 512 + k]; return; }
    i -= 131072;
    if (i < 262144) { int k = i >> 10, j = i & 1023; g_WhhT[i] = Whh[j * 256 + k]; return; }
    i -= 262144;
    if (i < 65536) { int m = i >> 8, n = i & 255; g_UdT[i] = Ud[n * 256 + m]; return; }
    i -= 65536;
    if (i < 1024) { g_bcomb[i] = bih[i] + bhh[i]; return; }
    i -= 1024;
    if (i < 512) {
        float s = 0.f;
        for (int j = 0; j < 256; ++j) s += vy[j] * Wy[j * 512 + i];
        g_weff[i] = s; return;
    }
    i -= 512;
    if (i == 0) {
        float s = 0.f;
        for (int j = 0; j < 256; ++j) s += vy[j] * Wyb[j];
        g_beff[0] = s + vyb[0];
    }
}

// ---------------- Ue = enc @ U_d^T : [131072,256] x [256,256] ----------------
__global__ __launch_bounds__(256) void ue_kernel(const float* __restrict__ enc)
{
    __shared__ __align__(16) float Es[32][20];
    int bt0 = blockIdx.x * 16;
    int n = threadIdx.x;
    float acc[16];
#pragma unroll
    for (int r = 0; r < 16; ++r) acc[r] = 0.f;

    for (int m0 = 0; m0 < 256; m0 += 32) {
        __syncthreads();
#pragma unroll
        for (int j = 0; j < 2; ++j) {
            int idx = n + j * 256;
            int r = idx >> 5, k = idx & 31;
            Es[k][r] = enc[(size_t)(bt0 + r) * 256 + m0 + k];
        }
        __syncthreads();
#pragma unroll 8
        for (int k = 0; k < 32; ++k) {
            float w = g_UdT[(m0 + k) * 256 + n];
            const float4* rp = (const float4*)&Es[k][0];
            float4 a = rp[0], b = rp[1], c = rp[2], d = rp[3];
            acc[0]  = fmaf(w, a.x, acc[0]);  acc[1]  = fmaf(w, a.y, acc[1]);
            acc[2]  = fmaf(w, a.z, acc[2]);  acc[3]  = fmaf(w, a.w, acc[3]);
            acc[4]  = fmaf(w, b.x, acc[4]);  acc[5]  = fmaf(w, b.y, acc[5]);
            acc[6]  = fmaf(w, b.z, acc[6]);  acc[7]  = fmaf(w, b.w, acc[7]);
            acc[8]  = fmaf(w, c.x, acc[8]);  acc[9]  = fmaf(w, c.y, acc[9]);
            acc[10] = fmaf(w, c.z, acc[10]); acc[11] = fmaf(w, c.w, acc[11]);
            acc[12] = fmaf(w, d.x, acc[12]); acc[13] = fmaf(w, d.y, acc[13]);
            acc[14] = fmaf(w, d.z, acc[14]); acc[15] = fmaf(w, d.w, acc[15]);
        }
    }
#pragma unroll
    for (int r = 0; r < 16; ++r)
        g_Ue[(size_t)(bt0 + r) * 256 + n] = acc[r];
}

// ---------------- persistent decoder: 147 blocks x 512 threads, G=14 batches/block ----------------
__global__ __launch_bounds__(512, 1) void decoder_kernel(
    const float* __restrict__ enc, const float* __restrict__ yin,
    const float* __restrict__ Wdb, const float* __restrict__ vd,
    const float* __restrict__ wt,  const float* __restrict__ wtb,
    const float* __restrict__ Wih, float* __restrict__ out)
{
    extern __shared__ __align__(16) float sm[];
    float* sD  = sm;            // [256][GP] hidden d
    float* sS  = sm + 4096;     // [256][GP] cell state
    float* sT1 = sm + 8192;     // [256][GP] temp: sigmoid(f)
    float* sT2 = sm + 12288;    // [256][GP] temp: tanh(c_new)
    float* sX1 = sm + 16384;    // [G][256]  x1
    float* sCt = sm + 19968;    // [G][256]  context c_t
    float* sL  = sm + 23552;    // [G][64]   scores / beta
    float* sYt = sm + 24448;    // [G]       y_tilda

    const int tid  = threadIdx.x;
    const int lane = tid & 31;
    const int wid  = tid >> 5;
    const int half = tid >> 8;   // 0 or 1 (uniform per warp)
    const int n    = tid & 255;
    const int base = blockIdx.x * G;

    // per-lane cached vectors
    float vdr[8], wtr[8];
#pragma unroll
    for (int i = 0; i < 8; ++i) { vdr[i] = vd[lane + 32 * i]; wtr[i] = wt[lane + 32 * i]; }

    // zero state
    for (int i = tid; i < 8192; i += 512) sD[i] = 0.f;   // covers sD and sS
    __syncthreads();

    for (int t = 0; t < CT; ++t) {
        // -------- Phase A: x1 = W_d @ [d; s] + b_d --------
        {
            const float* src = half ? sS : sD;
            const float* wp  = g_WdT + (half << 8) * 256 + n;
            float acc[G];
#pragma unroll
            for (int g = 0; g < G; ++g) acc[g] = 0.f;
#pragma unroll 4
            for (int k = 0; k < 256; ++k) {
                float w = wp[k << 8];
                float dv[G];
                LOAD14(dv, src + k * GP);
#pragma unroll
                for (int g = 0; g < G; ++g) acc[g] = fmaf(w, dv[g], acc[g]);
            }
            if (half == 0) {
#pragma unroll
                for (int g = 0; g < G; ++g) sX1[g * 256 + n] = acc[g];
            }
            __syncthreads();
            if (half == 1) {
                float bb = Wdb[n];
#pragma unroll
                for (int g = 0; g < G; ++g) sX1[g * 256 + n] += acc[g] + bb;
            }
            __syncthreads();
        }

        // -------- Phase B: attention scores l[g][t'] --------
        for (int p = wid; p < G * CT; p += 16) {
            int g = p >> 6, tt = p & 63;
            int b = min(base + g, CB - 1);
            const float* ue = g_Ue + ((size_t)b * CT + tt) * CM + lane;
            const float* x1 = sX1 + g * 256 + lane;
            float s = 0.f;
#pragma unroll
            for (int i = 0; i < 8; ++i) {
                float z = tanh_f(x1[32 * i] + ue[32 * i]);
                s = fmaf(z, vdr[i], s);
            }
            s = wredsum(s);
            if (lane == 0) sL[g * 64 + tt] = s;
        }
        __syncthreads();

        // -------- Phase B2: softmax over T_enc --------
        if (wid < G) {
            int g = wid;
            float l0 = sL[g * 64 + lane], l1 = sL[g * 64 + 32 + lane];
            float mx = wredmax(fmaxf(l0, l1));
            float e0 = fast_ex2((l0 - mx) * 1.4426950408889634f);
            float e1 = fast_ex2((l1 - mx) * 1.4426950408889634f);
            float ssum = wredsum(e0 + e1);
            float inv = fast_rcp(ssum);
            inv = inv * (2.f - ssum * inv);   // NR refine
            sL[g * 64 + lane]      = e0 * inv;
            sL[g * 64 + 32 + lane] = e1 * inv;
        }
        __syncthreads();

        // -------- Phase C: context c_t = beta @ enc --------
#pragma unroll
        for (int gi = 0; gi < 7; ++gi) {
            int g = half * 7 + gi;
            int b = min(base + g, CB - 1);
            const float* ep = enc + (size_t)b * CT * CM + n;
            const float* bp = sL + g * 64;
            float acc = 0.f;
#pragma unroll 8
            for (int tt = 0; tt < 64; ++tt)
                acc = fmaf(bp[tt], ep[(size_t)tt * 256], acc);
            sCt[g * 256 + n] = acc;
        }
        __syncthreads();

        // -------- Phase D: y_tilda --------
        if (wid < G) {
            int g = wid;
            float s = 0.f;
#pragma unroll
            for (int i = 0; i < 8; ++i)
                s = fmaf(sCt[g * 256 + lane + 32 * i], wtr[i], s);
            s = wredsum(s);
            if (lane == 0) {
                int b = min(base + g, CB - 1);
                float yt = yin[b * CT + t];
                sYt[g] = s + yt * wt[256] + wtb[0];
            }
        }
        __syncthreads();

        // -------- Phase E: LSTM cell --------
        {
            const int jA = n + half * 256;   // half0: i-gate, half1: f-gate
            const int jB = jA + 512;         // half0: g-gate, half1: o-gate
            float accA[G], accB[G];
#pragma unroll
            for (int g = 0; g < G; ++g) { accA[g] = 0.f; accB[g] = 0.f; }
            const float* wpA = g_WhhT + jA;
            const float* wpB = g_WhhT + jB;
#pragma unroll 2
            for (int k = 0; k < 256; ++k) {
                float w0 = wpA[k << 10];
                float w1 = wpB[k << 10];
                float dv[G];
                LOAD14(dv, sD + k * GP);
#pragma unroll
                for (int g = 0; g < G; ++g) {
                    accA[g] = fmaf(w0, dv[g], accA[g]);
                    accB[g] = fmaf(w1, dv[g], accB[g]);
                }
            }
            float bA = g_bcomb[jA], bB = g_bcomb[jB];
            float wiA = Wih[jA],   wiB = Wih[jB];
            float vA[G], vB[G];
#pragma unroll
            for (int g = 0; g < G; ++g) {
                float yt = sYt[g];
                float gA = accA[g] + bA + yt * wiA;
                float gB = accB[g] + bB + yt * wiB;
                vA[g] = sigm_f(gA);                              // sig(i) or sig(f)
                vB[g] = half ? sigm_f(gB) : tanh_f(gB);          // sig(o) or tanh(g)
            }
            if (half == 1) {
#pragma unroll
                for (int g = 0; g < G; ++g) sT1[n * GP + g] = vA[g];   // sig(f)
            }
            __syncthreads();
            if (half == 0) {
#pragma unroll
                for (int g = 0; g < G; ++g) {
                    float cn = fmaf(sT1[n * GP + g], sS[n * GP + g], vA[g] * vB[g]);
                    sS[n * GP + g]  = cn;
                    sT2[n * GP + g] = tanh_f(cn);
                }
            }
            __syncthreads();
            if (half == 1) {
#pragma unroll
                for (int g = 0; g < G; ++g)
                    sD[n * GP + g] = vB[g] * sT2[n * GP + g];     // h = sig(o)*tanh(c)
            }
            __syncthreads();
        }
    }

    // -------- Final head: y_Tp1 = [d, c_t] . w_eff + b_eff --------
    if (wid < G) {
        int g = wid;
        float s = 0.f;
#pragma unroll
        for (int i = 0; i < 8; ++i) {
            int m = lane + 32 * i;
            s = fmaf(sD[m * GP + g], g_weff[m], s);
            s = fmaf(sCt[g * 256 + m], g_weff[256 + m], s);
        }
        s = wredsum(s);
        if (lane == 0 && base + g < CB) out[base + g] = s + g_beff[0];
    }
    // -------- beta output (last step's beta) --------
    for (int p = tid; p < G * CT; p += 512) {
        int g = p >> 6, tt = p & 63;
        if (base + g < CB)
            out[CB + (size_t)(base + g) * CT + tt] = sL[g * 64 + tt];
    }
}

// ---------------- launcher ----------------
extern "C" void kernel_launch(void* const* d_in, const int* in_sizes, int n_in,
                              void* d_out, int out_size)
{
    (void)in_sizes; (void)n_in; (void)out_size;
    const float* enc = (const float*)d_in[0];
    const float* y   = (const float*)d_in[1];
    const float* Wd  = (const float*)d_in[2];
    const float* Wdb = (const float*)d_in[3];
    const float* Ud  = (const float*)d_in[4];
    const float* vd  = (const float*)d_in[5];
    const float* wt  = (const float*)d_in[6];
    const float* wtb = (const float*)d_in[7];
    const float* Wy  = (const float*)d_in[8];
    const float* Wyb = (const float*)d_in[9];
    const float* vy  = (const float*)d_in[10];
    const float* vyb = (const float*)d_in[11];
    const float* Wih = (const float*)d_in[12];
    const float* Whh = (const float*)d_in[13];
    const float* bih = (const float*)d_in[14];
    const float* bhh = (const float*)d_in[15];
    float* out = (float*)d_out;

    cudaFuncSetAttribute(decoder_kernel,
                         cudaFuncAttributeMaxDynamicSharedMemorySize, SMEM_BYTES);

    prep_kernel<<<1799, 256>>>(Wd, Whh, Ud, bih, bhh, vy, Wy, Wyb, vyb);
    ue_kernel<<<8192, 256>>>(enc);
    decoder_kernel<<<NBLK, 512, SMEM_BYTES>>>(enc, y, Wdb, vd, wt, wtb, Wih, out);
}

// round 2
// speedup vs baseline: 1.4641x; 1.4641x over previous
#include <cuda_runtime.h>
#include <cuda_fp16.h>

// Problem constants
#define CB   2048   // batch
#define CT   64     // T_enc == T_steps
#define CM   256    // M
#define CP   256    // P
#define G    14     // batches per block
#define GP   16     // padded G (float4-friendly row stride)
#define NBLK 147    // ceil(2048/14)

#define SMEM_FLOATS (4096*4 + 3584*2 + 896 + 16)
#define SMEM_BYTES  (SMEM_FLOATS * 4)

typedef unsigned long long ull;

// ---------------- device scratch (no allocation allowed) ----------------
__device__ __align__(16) __half  g_UeH[(size_t)CB * CT * CM];   // fp16 Ue  (64 MB)
__device__ __align__(16) __half  g_encH[(size_t)CB * CT * CM];  // fp16 enc (64 MB)
__device__ __align__(16) __half2 g_WdH[256 * 256];    // [k2][n] = (Wd[n][2k2], Wd[n][2k2+1])
__device__ __align__(16) __half2 g_WhhH[128 * 1024];  // [k2][j] = (Whh[j][2k2], Whh[j][2k2+1])
__device__ __align__(16) float   g_UdT[256 * 256];    // [m][n] = U_d_w[n][m]
__device__ float g_bcomb[1024];                       // b_ih + b_hh
__device__ float g_weff[512];                         // v_y @ W_y  (folded head)
__device__ float g_beff[1];                           // v_y @ W_y_b + v_y_b

// ---------------- f32x2 packed-FMA helpers ----------------
__device__ __forceinline__ ull pack2(float lo, float hi) {
    ull r; asm("mov.b64 %0, {%1, %2};" : "=l"(r) : "f"(lo), "f"(hi)); return r;
}
__device__ __forceinline__ ull bcast2(float x) { return pack2(x, x); }
__device__ __forceinline__ ull fma2(ull a, ull b, ull c) {
    ull d; asm("fma.rn.f32x2 %0, %1, %2, %3;" : "=l"(d) : "l"(a), "l"(b), "l"(c)); return d;
}
__device__ __forceinline__ float2 unpack2(ull v) {
    float2 f; asm("mov.b64 {%0, %1}, %2;" : "=f"(f.x), "=f"(f.y) : "l"(v)); return f;
}

// ---------------- fast math helpers ----------------
__device__ __forceinline__ float fast_ex2(float x) {
    float y; asm("ex2.approx.f32 %0, %1;" : "=f"(y) : "f"(x)); return y;
}
__device__ __forceinline__ float fast_rcp(float x) {
    float y; asm("rcp.approx.f32 %0, %1;" : "=f"(y) : "f"(x)); return y;
}
// tanh(x) = 1 - 2/(e^{2x}+1): ~1e-7 accurate, 2 MUFU ops
__device__ __forceinline__ float tanh_f(float x) {
    float e = fast_ex2(2.8853900817779268f * x);
    return fmaf(-2.f, fast_rcp(e + 1.f), 1.f);
}
__device__ __forceinline__ float sigm_f(float x) {
    float e = fast_ex2(-1.4426950408889634f * x);
    return fast_rcp(1.f + e);
}
__device__ __forceinline__ float wredsum(float s) {
#pragma unroll
    for (int o = 16; o; o >>= 1) s += __shfl_xor_sync(0xffffffffu, s, o);
    return s;
}
__device__ __forceinline__ float wredmax(float s) {
#pragma unroll
    for (int o = 16; o; o >>= 1) s = fmaxf(s, __shfl_xor_sync(0xffffffffu, s, o));
    return s;
}

// load 14 floats as 7 packed f32x2 (row is 64B-aligned: GP*4 = 64)
#define LOADP7(dv, ptr) {                                                   \
    const ulonglong2* _r = (const ulonglong2*)(ptr);                        \
    ulonglong2 _a = _r[0], _b = _r[1], _c = _r[2];                          \
    ull _d = ((const ull*)(ptr))[6];                                        \
    dv[0]=_a.x; dv[1]=_a.y; dv[2]=_b.x; dv[3]=_b.y;                         \
    dv[4]=_c.x; dv[5]=_c.y; dv[6]=_d; }

// ---------------- prep: transposes + folded head ----------------
__global__ void prep_kernel(const float* __restrict__ Wd,
                            const float* __restrict__ Whh,
                            const float* __restrict__ Ud,
                            const float* __restrict__ bih,
                            const float* __restrict__ bhh,
                            const float* __restrict__ vy,
                            const float* __restrict__ Wy,
                            const float* __restrict__ Wyb,
                            const float* __restrict__ vyb)
{
    int i = blockIdx.x * blockDim.x + threadIdx.x;
    if (i < 65536) {   // W_d -> half2 pairs over k
        int k2 = i >> 8, n = i & 255;
        g_WdH[i] = __floats2half2_rn(Wd[n * 512 + 2 * k2], Wd[n * 512 + 2 * k2 + 1]);
        return;
    }
    i -= 65536;
    if (i < 131072) {  // W_hh -> half2 pairs over k
        int k2 = i >> 10, j = i & 1023;
        g_WhhH[i] = __floats2half2_rn(Whh[j * 256 + 2 * k2], Whh[j * 256 + 2 * k2 + 1]);
        return;
    }
    i -= 131072;
    if (i < 65536) { int m = i >> 8, n = i & 255; g_UdT[i] = Ud[n * 256 + m]; return; }
    i -= 65536;
    if (i < 1024) { g_bcomb[i] = bih[i] + bhh[i]; return; }
    i -= 1024;
    if (i < 512) {
        float s = 0.f;
        for (int j = 0; j < 256; ++j) s += vy[j] * Wy[j * 512 + i];
        g_weff[i] = s; return;
    }
    i -= 512;
    if (i == 0) {
        float s = 0.f;
        for (int j = 0; j < 256; ++j) s += vy[j] * Wyb[j];
        g_beff[0] = s + vyb[0];
    }
}

// ---------------- Ue = enc @ U_d^T (f32x2), also emits fp16 enc copy ----------------
__global__ __launch_bounds__(256) void ue_kernel(const float* __restrict__ enc)
{
    __shared__ __align__(16) float Es[32][20];
    int bt0 = blockIdx.x * 16;
    int n = threadIdx.x;
    ull acc2[8];
#pragma unroll
    for (int j = 0; j < 8; ++j) acc2[j] = 0ull;

    for (int m0 = 0; m0 < 256; m0 += 32) {
        __syncthreads();
#pragma unroll
        for (int j = 0; j < 2; ++j) {
            int idx = n + j * 256;
            int r = idx >> 5, k = idx & 31;
            float v = enc[(size_t)(bt0 + r) * 256 + m0 + k];
            Es[k][r] = v;
            g_encH[(size_t)(bt0 + r) * 256 + m0 + k] = __float2half_rn(v);
        }
        __syncthreads();
#pragma unroll 8
        for (int k = 0; k < 32; ++k) {
            ull w2 = bcast2(g_UdT[(m0 + k) * 256 + n]);
            const ulonglong2* rp = (const ulonglong2*)&Es[k][0];
            ulonglong2 p0 = rp[0], p1 = rp[1], p2 = rp[2], p3 = rp[3];
            acc2[0] = fma2(w2, p0.x, acc2[0]);
            acc2[1] = fma2(w2, p0.y, acc2[1]);
            acc2[2] = fma2(w2, p1.x, acc2[2]);
            acc2[3] = fma2(w2, p1.y, acc2[3]);
            acc2[4] = fma2(w2, p2.x, acc2[4]);
            acc2[5] = fma2(w2, p2.y, acc2[5]);
            acc2[6] = fma2(w2, p3.x, acc2[6]);
            acc2[7] = fma2(w2, p3.y, acc2[7]);
        }
    }
#pragma unroll
    for (int j = 0; j < 8; ++j) {
        float2 f = unpack2(acc2[j]);
        g_UeH[(size_t)(bt0 + 2 * j)     * 256 + n] = __float2half_rn(f.x);
        g_UeH[(size_t)(bt0 + 2 * j + 1) * 256 + n] = __float2half_rn(f.y);
    }
}

// ---------------- persistent decoder: 147 blocks x 512 threads, G=14 batches/block ----------------
__global__ __launch_bounds__(512, 1) void decoder_kernel(
    const float* __restrict__ yin,
    const float* __restrict__ Wdb, const float* __restrict__ vd,
    const float* __restrict__ wt,  const float* __restrict__ wtb,
    const float* __restrict__ Wih, float* __restrict__ out)
{
    extern __shared__ __align__(16) float sm[];
    float* sD  = sm;            // [256][GP] hidden d
    float* sS  = sm + 4096;     // [256][GP] cell state
    float* sT1 = sm + 8192;     // [256][GP] temp: sigmoid(f)
    float* sT2 = sm + 12288;    // [256][GP] temp: tanh(c_new)
    float* sX1 = sm + 16384;    // [G][256]  x1
    float* sCt = sm + 19968;    // [G][256]  context c_t
    float* sL  = sm + 23552;    // [G][64]   scores / beta
    float* sYt = sm + 24448;    // [G]       y_tilda

    const int tid  = threadIdx.x;
    const int lane = tid & 31;
    const int wid  = tid >> 5;
    const int half = tid >> 8;   // 0 or 1 (uniform per warp)
    const int n    = tid & 255;
    const int base = blockIdx.x * G;

    // per-lane cached vectors: vd packed f32x2 over 8 consecutive m's, wt stride-32
    ull vd2[4];
    float wtr[8];
#pragma unroll
    for (int j = 0; j < 4; ++j)
        vd2[j] = pack2(vd[lane * 8 + 2 * j], vd[lane * 8 + 2 * j + 1]);
#pragma unroll
    for (int i = 0; i < 8; ++i) wtr[i] = wt[lane + 32 * i];

    // zero state (covers sD and sS)
    for (int i = tid; i < 8192; i += 512) sD[i] = 0.f;
    __syncthreads();

    for (int t = 0; t < CT; ++t) {
        // -------- Phase A: x1 = W_d @ [d; s] + b_d  (f32x2, fp16 weights) --------
        {
            const float* src = half ? sS : sD;
            const __half2* wp = g_WdH + (half << 15) + n;  // (half*128)*256 + n
            ull acc[7];
#pragma unroll
            for (int j = 0; j < 7; ++j) acc[j] = 0ull;
#pragma unroll 2
            for (int k2 = 0; k2 < 128; ++k2) {
                float2 wf = __half22float2(wp[k2 << 8]);
                ull w0 = bcast2(wf.x), w1 = bcast2(wf.y);
                ull dv[7];
                LOADP7(dv, src + (2 * k2) * GP);
#pragma unroll
                for (int j = 0; j < 7; ++j) acc[j] = fma2(w0, dv[j], acc[j]);
                LOADP7(dv, src + (2 * k2 + 1) * GP);
#pragma unroll
                for (int j = 0; j < 7; ++j) acc[j] = fma2(w1, dv[j], acc[j]);
            }
            float av[G];
#pragma unroll
            for (int j = 0; j < 7; ++j) {
                float2 f = unpack2(acc[j]);
                av[2 * j] = f.x; av[2 * j + 1] = f.y;
            }
            if (half == 0) {
#pragma unroll
                for (int g = 0; g < G; ++g) sX1[g * 256 + n] = av[g];
            }
            __syncthreads();
            if (half == 1) {
                float bb = Wdb[n];
#pragma unroll
                for (int g = 0; g < G; ++g) sX1[g * 256 + n] += av[g] + bb;
            }
            __syncthreads();
        }

        // -------- Phase B: attention scores l[g][t'] (fp16 Ue, vectorized) --------
        for (int p = wid; p < G * CT; p += 16) {
            int g = p >> 6, tt = p & 63;
            int b = min(base + g, CB - 1);
            uint4 u = *((const uint4*)(g_UeH + (((size_t)b * CT + tt) << 8)) + lane);
            const float4* xp = (const float4*)(sX1 + g * 256) + (lane << 1);
            float4 xa = xp[0], xb = xp[1];
            const __half2* uh = (const __half2*)&u;
            float2 u0 = __half22float2(uh[0]), u1 = __half22float2(uh[1]);
            float2 u2 = __half22float2(uh[2]), u3 = __half22float2(uh[3]);
            float z0 = tanh_f(xa.x + u0.x), z1 = tanh_f(xa.y + u0.y);
            float z2 = tanh_f(xa.z + u1.x), z3 = tanh_f(xa.w + u1.y);
            float z4 = tanh_f(xb.x + u2.x), z5 = tanh_f(xb.y + u2.y);
            float z6 = tanh_f(xb.z + u3.x), z7 = tanh_f(xb.w + u3.y);
            ull acc = 0ull;
            acc = fma2(pack2(z0, z1), vd2[0], acc);
            acc = fma2(pack2(z2, z3), vd2[1], acc);
            acc = fma2(pack2(z4, z5), vd2[2], acc);
            acc = fma2(pack2(z6, z7), vd2[3], acc);
            float2 f = unpack2(acc);
            float s = wredsum(f.x + f.y);
            if (lane == 0) sL[g * 64 + tt] = s;
        }
        __syncthreads();

        // -------- Phase B2: softmax over T_enc --------
        if (wid < G) {
            int g = wid;
            float l0 = sL[g * 64 + lane], l1 = sL[g * 64 + 32 + lane];
            float mx = wredmax(fmaxf(l0, l1));
            float e0 = fast_ex2((l0 - mx) * 1.4426950408889634f);
            float e1 = fast_ex2((l1 - mx) * 1.4426950408889634f);
            float ssum = wredsum(e0 + e1);
            float inv = fast_rcp(ssum);
            inv = inv * (2.f - ssum * inv);   // NR refine
            sL[g * 64 + lane]      = e0 * inv;
            sL[g * 64 + 32 + lane] = e1 * inv;
        }
        __syncthreads();

        // -------- Phase C: context c_t = beta @ enc (fp16 enc, warp-per-g) --------
        if (wid < G) {
            int g = wid;
            int b = min(base + g, CB - 1);
            const uint4* ep = (const uint4*)(g_encH + ((size_t)b * CT << 8)) + lane;
            ull a0 = 0ull, a1 = 0ull, a2 = 0ull, a3 = 0ull;
#pragma unroll 4
            for (int tt = 0; tt < 64; ++tt) {
                uint4 u = ep[tt << 5];
                ull b2 = bcast2(sL[g * 64 + tt]);
                const __half2* uh = (const __half2*)&u;
                float2 e0 = __half22float2(uh[0]), e1 = __half22float2(uh[1]);
                float2 e2 = __half22float2(uh[2]), e3 = __half22float2(uh[3]);
                a0 = fma2(b2, pack2(e0.x, e0.y), a0);
                a1 = fma2(b2, pack2(e1.x, e1.y), a1);
                a2 = fma2(b2, pack2(e2.x, e2.y), a2);
                a3 = fma2(b2, pack2(e3.x, e3.y), a3);
            }
            float* cp = sCt + g * 256 + lane * 8;
            float2 f0 = unpack2(a0), f1 = unpack2(a1);
            float2 f2 = unpack2(a2), f3 = unpack2(a3);
            ((float4*)cp)[0] = make_float4(f0.x, f0.y, f1.x, f1.y);
            ((float4*)cp)[1] = make_float4(f2.x, f2.y, f3.x, f3.y);
        }
        __syncthreads();

        // -------- Phase D: y_tilda --------
        if (wid < G) {
            int g = wid;
            float s = 0.f;
#pragma unroll
            for (int i = 0; i < 8; ++i)
                s = fmaf(sCt[g * 256 + lane + 32 * i], wtr[i], s);
            s = wredsum(s);
            if (lane == 0) {
                int b = min(base + g, CB - 1);
                float yt = yin[b * CT + t];
                sYt[g] = s + yt * wt[256] + wtb[0];
            }
        }
        __syncthreads();

        // -------- Phase E: LSTM cell (f32x2, fp16 weights) --------
        {
            const int jA = n + (half << 8);  // half0: i-gate, half1: f-gate
            const int jB = jA + 512;         // half0: g-gate, half1: o-gate
            ull aA[7], aB[7];
#pragma unroll
            for (int j = 0; j < 7; ++j) { aA[j] = 0ull; aB[j] = 0ull; }
            const __half2* wA = g_WhhH + jA;
            const __half2* wB = g_WhhH + jB;
#pragma unroll 2
            for (int k2 = 0; k2 < 128; ++k2) {
                float2 fA = __half22float2(wA[k2 << 10]);
                float2 fB = __half22float2(wB[k2 << 10]);
                ull a0 = bcast2(fA.x), a1 = bcast2(fA.y);
                ull b0 = bcast2(fB.x), b1 = bcast2(fB.y);
                ull dv[7];
                LOADP7(dv, sD + (2 * k2) * GP);
#pragma unroll
                for (int j = 0; j < 7; ++j) {
                    aA[j] = fma2(a0, dv[j], aA[j]);
                    aB[j] = fma2(b0, dv[j], aB[j]);
                }
                LOADP7(dv, sD + (2 * k2 + 1) * GP);
#pragma unroll
                for (int j = 0; j < 7; ++j) {
                    aA[j] = fma2(a1, dv[j], aA[j]);
                    aB[j] = fma2(b1, dv[j], aB[j]);
                }
            }
            float accA[G], accB[G];
#pragma unroll
            for (int j = 0; j < 7; ++j) {
                float2 fa = unpack2(aA[j]), fb = unpack2(aB[j]);
                accA[2 * j] = fa.x; accA[2 * j + 1] = fa.y;
                accB[2 * j] = fb.x; accB[2 * j + 1] = fb.y;
            }
            float bA = g_bcomb[jA], bB = g_bcomb[jB];
            float wiA = Wih[jA],   wiB = Wih[jB];
            float vA[G], vB[G];
#pragma unroll
            for (int g = 0; g < G; ++g) {
                float yt = sYt[g];
                float gA = accA[g] + bA + yt * wiA;
                float gB = accB[g] + bB + yt * wiB;
                vA[g] = sigm_f(gA);                              // sig(i) or sig(f)
                vB[g] = half ? sigm_f(gB) : tanh_f(gB);          // sig(o) or tanh(g)
            }
            if (half == 1) {
#pragma unroll
                for (int g = 0; g < G; ++g) sT1[n * GP + g] = vA[g];   // sig(f)
            }
            __syncthreads();
            if (half == 0) {
#pragma unroll
                for (int g = 0; g < G; ++g) {
                    float cn = fmaf(sT1[n * GP + g], sS[n * GP + g], vA[g] * vB[g]);
                    sS[n * GP + g]  = cn;
                    sT2[n * GP + g] = tanh_f(cn);
                }
            }
            __syncthreads();
            if (half == 1) {
#pragma unroll
                for (int g = 0; g < G; ++g)
                    sD[n * GP + g] = vB[g] * sT2[n * GP + g];     // h = sig(o)*tanh(c)
            }
            __syncthreads();
        }
    }

    // -------- Final head: y_Tp1 = [d, c_t] . w_eff + b_eff --------
    if (wid < G) {
        int g = wid;
        float s = 0.f;
#pragma unroll
        for (int i = 0; i < 8; ++i) {
            int m = lane + 32 * i;
            s = fmaf(sD[m * GP + g], g_weff[m], s);
            s = fmaf(sCt[g * 256 + m], g_weff[256 + m], s);
        }
        s = wredsum(s);
        if (lane == 0 && base + g < CB) out[base + g] = s + g_beff[0];
    }
    // -------- beta output (last step's beta) --------
    for (int p = tid; p < G * CT; p += 512) {
        int g = p >> 6, tt = p & 63;
        if (base + g < CB)
            out[CB + (size_t)(base + g) * CT + tt] = sL[g * 64 + tt];
    }
}

// ---------------- launcher ----------------
extern "C" void kernel_launch(void* const* d_in, const int* in_sizes, int n_in,
                              void* d_out, int out_size)
{
    (void)in_sizes; (void)n_in; (void)out_size;
    const float* enc = (const float*)d_in[0];
    const float* y   = (const float*)d_in[1];
    const float* Wd  = (const float*)d_in[2];
    const float* Wdb = (const float*)d_in[3];
    const float* Ud  = (const float*)d_in[4];
    const float* vd  = (const float*)d_in[5];
    const float* wt  = (const float*)d_in[6];
    const float* wtb = (const float*)d_in[7];
    const float* Wy  = (const float*)d_in[8];
    const float* Wyb = (const float*)d_in[9];
    const float* vy  = (const float*)d_in[10];
    const float* vyb = (const float*)d_in[11];
    const float* Wih = (const float*)d_in[12];
    const float* Whh = (const float*)d_in[13];
    const float* bih = (const float*)d_in[14];
    const float* bhh = (const float*)d_in[15];
    float* out = (float*)d_out;

    cudaFuncSetAttribute(decoder_kernel,
                         cudaFuncAttributeMaxDynamicSharedMemorySize, SMEM_BYTES);

    prep_kernel<<<1031, 256>>>(Wd, Whh, Ud, bih, bhh, vy, Wy, Wyb, vyb);
    ue_kernel<<<8192, 256>>>(enc);
    decoder_kernel<<<NBLK, 512, SMEM_BYTES>>>(y, Wdb, vd, wt, wtb, Wih, out);
}

// round 3
// speedup vs baseline: 2.3359x; 1.5955x over previous
#include <cuda_runtime.h>
#include <cuda_fp16.h>

// Problem constants
#define CB   2048   // batch
#define CT   64     // T_enc == T_steps
#define CM   256    // M
#define CP   256    // P
#define G    14     // batches per block
#define GP   16     // padded G (float4-friendly row stride)
#define NBLK 147    // ceil(2048/14)

#define SMEM_FLOATS (4096*4 + 3584*2 + 896 + 16)
#define SMEM_BYTES  (SMEM_FLOATS * 4)

typedef unsigned long long ull;

// ---------------- device scratch (no allocation allowed) ----------------
__device__ __align__(16) __half  g_UeH[(size_t)CB * CT * CM];   // fp16 Ue  (64 MB)
__device__ __align__(16) __half  g_encH[(size_t)CB * CT * CM];  // fp16 enc (64 MB)
__device__ __align__(16) __half2 g_WdH[256 * 256];    // [k2][n] = (Wd[n][2k2], Wd[n][2k2+1])
__device__ __align__(16) __half2 g_WhhH[128 * 1024];  // [k2][j] = (Whh[j][2k2], Whh[j][2k2+1])
__device__ __align__(16) float   g_UdT[256 * 256];    // [m][n] = U_d_w[n][m]
__device__ float g_bcomb[1024];                       // b_ih + b_hh
__device__ float g_weff[512];                         // v_y @ W_y  (folded head)
__device__ float g_beff[1];                           // v_y @ W_y_b + v_y_b

// ---------------- f32x2 packed-FMA helpers ----------------
__device__ __forceinline__ ull pack2(float lo, float hi) {
    ull r; asm("mov.b64 %0, {%1, %2};" : "=l"(r) : "f"(lo), "f"(hi)); return r;
}
__device__ __forceinline__ ull bcast2(float x) { return pack2(x, x); }
__device__ __forceinline__ ull fma2(ull a, ull b, ull c) {
    ull d; asm("fma.rn.f32x2 %0, %1, %2, %3;" : "=l"(d) : "l"(a), "l"(b), "l"(c)); return d;
}
__device__ __forceinline__ float2 unpack2(ull v) {
    float2 f; asm("mov.b64 {%0, %1}, %2;" : "=f"(f.x), "=f"(f.y) : "l"(v)); return f;
}

// ---------------- fast math helpers ----------------
__device__ __forceinline__ float fast_ex2(float x) {
    float y; asm("ex2.approx.f32 %0, %1;" : "=f"(y) : "f"(x)); return y;
}
__device__ __forceinline__ float fast_rcp(float x) {
    float y; asm("rcp.approx.f32 %0, %1;" : "=f"(y) : "f"(x)); return y;
}
// exact-ish tanh: 2 MUFU (used in LSTM recurrence path)
__device__ __forceinline__ float tanh_f(float x) {
    float e = fast_ex2(2.8853900817779268f * x);
    return fmaf(-2.f, fast_rcp(e + 1.f), 1.f);
}
// HW tanh: 1 MUFU (attention scores only)
__device__ __forceinline__ float tanh_a(float x) {
    float y; asm("tanh.approx.f32 %0, %1;" : "=f"(y) : "f"(x)); return y;
}
__device__ __forceinline__ float sigm_f(float x) {
    float e = fast_ex2(-1.4426950408889634f * x);
    return fast_rcp(1.f + e);
}
__device__ __forceinline__ float wredsum(float s) {
#pragma unroll
    for (int o = 16; o; o >>= 1) s += __shfl_xor_sync(0xffffffffu, s, o);
    return s;
}
__device__ __forceinline__ float wredmax(float s) {
#pragma unroll
    for (int o = 16; o; o >>= 1) s = fmaxf(s, __shfl_xor_sync(0xffffffffu, s, o));
    return s;
}

// load 14 floats as 7 packed f32x2 (row is 64B-aligned: GP*4 = 64)
#define LOADP7(dv, ptr) {                                                   \
    const ulonglong2* _r = (const ulonglong2*)(ptr);                        \
    ulonglong2 _a = _r[0], _b = _r[1], _c = _r[2];                          \
    ull _d = ((const ull*)(ptr))[6];                                        \
    dv[0]=_a.x; dv[1]=_a.y; dv[2]=_b.x; dv[3]=_b.y;                         \
    dv[4]=_c.x; dv[5]=_c.y; dv[6]=_d; }

// ---------------- prep: transposes + folded head ----------------
__global__ void prep_kernel(const float* __restrict__ Wd,
                            const float* __restrict__ Whh,
                            const float* __restrict__ Ud,
                            const float* __restrict__ bih,
                            const float* __restrict__ bhh,
                            const float* __restrict__ vy,
                            const float* __restrict__ Wy,
                            const float* __restrict__ Wyb,
                            const float* __restrict__ vyb)
{
    int i = blockIdx.x * blockDim.x + threadIdx.x;
    if (i < 65536) {   // W_d -> half2 pairs over k
        int k2 = i >> 8, n = i & 255;
        g_WdH[i] = __floats2half2_rn(Wd[n * 512 + 2 * k2], Wd[n * 512 + 2 * k2 + 1]);
        return;
    }
    i -= 65536;
    if (i < 131072) {  // W_hh -> half2 pairs over k
        int k2 = i >> 10, j = i & 1023;
        g_WhhH[i] = __floats2half2_rn(Whh[j * 256 + 2 * k2], Whh[j * 256 + 2 * k2 + 1]);
        return;
    }
    i -= 131072;
    if (i < 65536) { int m = i >> 8, n = i & 255; g_UdT[i] = Ud[n * 256 + m]; return; }
    i -= 65536;
    if (i < 1024) { g_bcomb[i] = bih[i] + bhh[i]; return; }
    i -= 1024;
    if (i < 512) {
        float s = 0.f;
        for (int j = 0; j < 256; ++j) s += vy[j] * Wy[j * 512 + i];
        g_weff[i] = s; return;
    }
    i -= 512;
    if (i == 0) {
        float s = 0.f;
        for (int j = 0; j < 256; ++j) s += vy[j] * Wyb[j];
        g_beff[0] = s + vyb[0];
    }
}

// ---------------- Ue = enc @ U_d^T (f32x2), also emits fp16 enc copy ----------------
__global__ __launch_bounds__(256) void ue_kernel(const float* __restrict__ enc)
{
    __shared__ __align__(16) float Es[32][20];
    int bt0 = blockIdx.x * 16;
    int n = threadIdx.x;
    ull acc2[8];
#pragma unroll
    for (int j = 0; j < 8; ++j) acc2[j] = 0ull;

    for (int m0 = 0; m0 < 256; m0 += 32) {
        __syncthreads();
#pragma unroll
        for (int j = 0; j < 2; ++j) {
            int idx = n + j * 256;
            int r = idx >> 5, k = idx & 31;
            float v = enc[(size_t)(bt0 + r) * 256 + m0 + k];
            Es[k][r] = v;
            g_encH[(size_t)(bt0 + r) * 256 + m0 + k] = __float2half_rn(v);
        }
        __syncthreads();
#pragma unroll 8
        for (int k = 0; k < 32; ++k) {
            ull w2 = bcast2(g_UdT[(m0 + k) * 256 + n]);
            const ulonglong2* rp = (const ulonglong2*)&Es[k][0];
            ulonglong2 p0 = rp[0], p1 = rp[1], p2 = rp[2], p3 = rp[3];
            acc2[0] = fma2(w2, p0.x, acc2[0]);
            acc2[1] = fma2(w2, p0.y, acc2[1]);
            acc2[2] = fma2(w2, p1.x, acc2[2]);
            acc2[3] = fma2(w2, p1.y, acc2[3]);
            acc2[4] = fma2(w2, p2.x, acc2[4]);
            acc2[5] = fma2(w2, p2.y, acc2[5]);
            acc2[6] = fma2(w2, p3.x, acc2[6]);
            acc2[7] = fma2(w2, p3.y, acc2[7]);
        }
    }
#pragma unroll
    for (int j = 0; j < 8; ++j) {
        float2 f = unpack2(acc2[j]);
        g_UeH[(size_t)(bt0 + 2 * j)     * 256 + n] = __float2half_rn(f.x);
        g_UeH[(size_t)(bt0 + 2 * j + 1) * 256 + n] = __float2half_rn(f.y);
    }
}

// ---------------- persistent decoder: 147 blocks x 512 threads, G=14 batches/block ----------------
__global__ __launch_bounds__(512, 1) void decoder_kernel(
    const float* __restrict__ yin,
    const float* __restrict__ Wdb, const float* __restrict__ vd,
    const float* __restrict__ wt,  const float* __restrict__ wtb,
    const float* __restrict__ Wih, float* __restrict__ out)
{
    extern __shared__ __align__(16) float sm[];
    float* sD  = sm;            // [256][GP] hidden d
    float* sS  = sm + 4096;     // [256][GP] cell state
    float* sT1 = sm + 8192;     // [256][GP] temp: sigmoid(f)
    float* sT2 = sm + 12288;    // [256][GP] temp: tanh(c_new)
    float* sX1 = sm + 16384;    // [G][256]  x1
    float* sCt = sm + 19968;    // [G][256]  context c_t
    float* sL  = sm + 23552;    // [G][64]   scores / beta
    float* sYt = sm + 24448;    // [G]       y_tilda

    const int tid  = threadIdx.x;
    const int lane = tid & 31;
    const int wid  = tid >> 5;
    const int half = tid >> 8;   // 0 or 1 (uniform per warp)
    const int n    = tid & 255;
    const int base = blockIdx.x * G;

    // per-lane cached vectors: vd packed f32x2 over 8 consecutive m's, wt stride-32
    ull vd2[4];
    float wtr[8];
#pragma unroll
    for (int j = 0; j < 4; ++j)
        vd2[j] = pack2(vd[lane * 8 + 2 * j], vd[lane * 8 + 2 * j + 1]);
#pragma unroll
    for (int i = 0; i < 8; ++i) wtr[i] = wt[lane + 32 * i];

    // zero state (covers sD and sS)
    for (int i = tid; i < 8192; i += 512) sD[i] = 0.f;
    __syncthreads();

    for (int t = 0; t < CT; ++t) {
        // -------- Phase A: x1 = W_d @ [d; s] + b_d  (f32x2, fp16 weights, prefetch d=8) --------
        {
            const float* src = half ? sS : sD;
            const __half2* wp = g_WdH + (half << 15) + n;  // (half*128)*256 + n
            ull acc[7];
#pragma unroll
            for (int j = 0; j < 7; ++j) acc[j] = 0ull;

            __half2 wbuf[8];
#pragma unroll
            for (int j = 0; j < 8; ++j) wbuf[j] = wp[j << 8];

            auto abody = [&](int k2, bool pf) {
                float2 wf = __half22float2(wbuf[k2 & 7]);
                if (pf) wbuf[k2 & 7] = wp[(k2 + 8) << 8];
                ull w0 = bcast2(wf.x), w1 = bcast2(wf.y);
                ull dv[7];
                LOADP7(dv, src + (2 * k2) * GP);
#pragma unroll
                for (int j = 0; j < 7; ++j) acc[j] = fma2(w0, dv[j], acc[j]);
                LOADP7(dv, src + (2 * k2 + 1) * GP);
#pragma unroll
                for (int j = 0; j < 7; ++j) acc[j] = fma2(w1, dv[j], acc[j]);
            };
#pragma unroll 8
            for (int k2 = 0; k2 < 120; ++k2) abody(k2, true);
#pragma unroll
            for (int k2 = 120; k2 < 128; ++k2) abody(k2, false);

            float av[G];
#pragma unroll
            for (int j = 0; j < 7; ++j) {
                float2 f = unpack2(acc[j]);
                av[2 * j] = f.x; av[2 * j + 1] = f.y;
            }
            if (half == 0) {
#pragma unroll
                for (int g = 0; g < G; ++g) sX1[g * 256 + n] = av[g];
            }
            __syncthreads();
            if (half == 1) {
                float bb = Wdb[n];
#pragma unroll
                for (int g = 0; g < G; ++g) sX1[g * 256 + n] += av[g] + bb;
            }
            __syncthreads();
        }

        // -------- Phase B: attention scores, 4-way task interleave (fp16 Ue, MUFU.TANH) --------
        for (int p0 = wid; p0 < G * CT; p0 += 64) {
            uint4 u[4];
#pragma unroll
            for (int j = 0; j < 4; ++j) {
                int p = p0 + 16 * j;
                int b = min(base + (p >> 6), CB - 1);
                u[j] = *((const uint4*)(g_UeH + (((size_t)b * CT + (p & 63)) << 8)) + lane);
            }
            float sres[4];
#pragma unroll
            for (int j = 0; j < 4; ++j) {
                int p = p0 + 16 * j;
                int g = p >> 6;
                const float4* xp = (const float4*)(sX1 + g * 256) + (lane << 1);
                float4 xa = xp[0], xb = xp[1];
                const __half2* uh = (const __half2*)&u[j];
                float2 u0 = __half22float2(uh[0]), u1 = __half22float2(uh[1]);
                float2 u2 = __half22float2(uh[2]), u3 = __half22float2(uh[3]);
                float z0 = tanh_a(xa.x + u0.x), z1 = tanh_a(xa.y + u0.y);
                float z2 = tanh_a(xa.z + u1.x), z3 = tanh_a(xa.w + u1.y);
                float z4 = tanh_a(xb.x + u2.x), z5 = tanh_a(xb.y + u2.y);
                float z6 = tanh_a(xb.z + u3.x), z7 = tanh_a(xb.w + u3.y);
                ull acc = 0ull;
                acc = fma2(pack2(z0, z1), vd2[0], acc);
                acc = fma2(pack2(z2, z3), vd2[1], acc);
                acc = fma2(pack2(z4, z5), vd2[2], acc);
                acc = fma2(pack2(z6, z7), vd2[3], acc);
                float2 f = unpack2(acc);
                sres[j] = f.x + f.y;
            }
            // 4 interleaved warp reductions (independent shuffle chains)
#pragma unroll
            for (int o = 16; o; o >>= 1) {
#pragma unroll
                for (int j = 0; j < 4; ++j)
                    sres[j] += __shfl_xor_sync(0xffffffffu, sres[j], o);
            }
            if (lane == 0) {
#pragma unroll
                for (int j = 0; j < 4; ++j) sL[p0 + 16 * j] = sres[j];
            }
        }
        __syncthreads();

        // -------- Phase B2: softmax over T_enc --------
        if (wid < G) {
            int g = wid;
            float l0 = sL[g * 64 + lane], l1 = sL[g * 64 + 32 + lane];
            float mx = wredmax(fmaxf(l0, l1));
            float e0 = fast_ex2((l0 - mx) * 1.4426950408889634f);
            float e1 = fast_ex2((l1 - mx) * 1.4426950408889634f);
            float ssum = wredsum(e0 + e1);
            float inv = fast_rcp(ssum);
            inv = inv * (2.f - ssum * inv);   // NR refine
            sL[g * 64 + lane]      = e0 * inv;
            sL[g * 64 + 32 + lane] = e1 * inv;
        }
        __syncthreads();

        // -------- Phase C: context c_t = beta @ enc (fp16 enc, 8-batched loads, MLP 8) --------
        if (wid < G) {
            int g = wid;
            int b = min(base + g, CB - 1);
            const uint4* ep = (const uint4*)(g_encH + ((size_t)b * CT << 8)) + lane;
            ull a0 = 0ull, a1 = 0ull, a2 = 0ull, a3 = 0ull;
            for (int t0 = 0; t0 < 64; t0 += 8) {
                uint4 uu[8];
#pragma unroll
                for (int j = 0; j < 8; ++j) uu[j] = ep[(t0 + j) << 5];
#pragma unroll
                for (int j = 0; j < 8; ++j) {
                    ull b2 = bcast2(sL[g * 64 + t0 + j]);
                    const __half2* uh = (const __half2*)&uu[j];
                    float2 e0 = __half22float2(uh[0]), e1 = __half22float2(uh[1]);
                    float2 e2 = __half22float2(uh[2]), e3 = __half22float2(uh[3]);
                    a0 = fma2(b2, pack2(e0.x, e0.y), a0);
                    a1 = fma2(b2, pack2(e1.x, e1.y), a1);
                    a2 = fma2(b2, pack2(e2.x, e2.y), a2);
                    a3 = fma2(b2, pack2(e3.x, e3.y), a3);
                }
            }
            float* cp = sCt + g * 256 + lane * 8;
            float2 f0 = unpack2(a0), f1 = unpack2(a1);
            float2 f2 = unpack2(a2), f3 = unpack2(a3);
            ((float4*)cp)[0] = make_float4(f0.x, f0.y, f1.x, f1.y);
            ((float4*)cp)[1] = make_float4(f2.x, f2.y, f3.x, f3.y);
        }
        __syncthreads();

        // -------- Phase D: y_tilda --------
        if (wid < G) {
            int g = wid;
            float s = 0.f;
#pragma unroll
            for (int i = 0; i < 8; ++i)
                s = fmaf(sCt[g * 256 + lane + 32 * i], wtr[i], s);
            s = wredsum(s);
            if (lane == 0) {
                int b = min(base + g, CB - 1);
                float yt = yin[b * CT + t];
                sYt[g] = s + yt * wt[256] + wtb[0];
            }
        }
        __syncthreads();

        // -------- Phase E: LSTM cell (f32x2, fp16 weights, prefetch d=4 x2 streams) --------
        {
            const int jA = n + (half << 8);  // half0: i-gate, half1: f-gate
            const int jB = jA + 512;         // half0: g-gate, half1: o-gate
            ull aA[7], aB[7];
#pragma unroll
            for (int j = 0; j < 7; ++j) { aA[j] = 0ull; aB[j] = 0ull; }
            const __half2* wA = g_WhhH + jA;
            const __half2* wB = g_WhhH + jB;

            __half2 wbA[4], wbB[4];
#pragma unroll
            for (int j = 0; j < 4; ++j) { wbA[j] = wA[j << 10]; wbB[j] = wB[j << 10]; }

            auto ebody = [&](int k2, bool pf) {
                float2 fA = __half22float2(wbA[k2 & 3]);
                float2 fB = __half22float2(wbB[k2 & 3]);
                if (pf) { wbA[k2 & 3] = wA[(k2 + 4) << 10]; wbB[k2 & 3] = wB[(k2 + 4) << 10]; }
                ull a0 = bcast2(fA.x), a1 = bcast2(fA.y);
                ull b0 = bcast2(fB.x), b1 = bcast2(fB.y);
                ull dv[7];
                LOADP7(dv, sD + (2 * k2) * GP);
#pragma unroll
                for (int j = 0; j < 7; ++j) {
                    aA[j] = fma2(a0, dv[j], aA[j]);
                    aB[j] = fma2(b0, dv[j], aB[j]);
                }
                LOADP7(dv, sD + (2 * k2 + 1) * GP);
#pragma unroll
                for (int j = 0; j < 7; ++j) {
                    aA[j] = fma2(a1, dv[j], aA[j]);
                    aB[j] = fma2(b1, dv[j], aB[j]);
                }
            };
#pragma unroll 4
            for (int k2 = 0; k2 < 124; ++k2) ebody(k2, true);
#pragma unroll
            for (int k2 = 124; k2 < 128; ++k2) ebody(k2, false);

            float accA[G], accB[G];
#pragma unroll
            for (int j = 0; j < 7; ++j) {
                float2 fa = unpack2(aA[j]), fb = unpack2(aB[j]);
                accA[2 * j] = fa.x; accA[2 * j + 1] = fa.y;
                accB[2 * j] = fb.x; accB[2 * j + 1] = fb.y;
            }
            float bA = g_bcomb[jA], bB = g_bcomb[jB];
            float wiA = Wih[jA],   wiB = Wih[jB];
            float vA[G], vB[G];
#pragma unroll
            for (int g = 0; g < G; ++g) {
                float yt = sYt[g];
                float gA = accA[g] + bA + yt * wiA;
                float gB = accB[g] + bB + yt * wiB;
                vA[g] = sigm_f(gA);                              // sig(i) or sig(f)
                vB[g] = half ? sigm_f(gB) : tanh_f(gB);          // sig(o) or tanh(g)
            }
            if (half == 1) {
#pragma unroll
                for (int g = 0; g < G; ++g) sT1[n * GP + g] = vA[g];   // sig(f)
            }
            __syncthreads();
            if (half == 0) {
#pragma unroll
                for (int g = 0; g < G; ++g) {
                    float cn = fmaf(sT1[n * GP + g], sS[n * GP + g], vA[g] * vB[g]);
                    sS[n * GP + g]  = cn;
                    sT2[n * GP + g] = tanh_f(cn);
                }
            }
            __syncthreads();
            if (half == 1) {
#pragma unroll
                for (int g = 0; g < G; ++g)
                    sD[n * GP + g] = vB[g] * sT2[n * GP + g];     // h = sig(o)*tanh(c)
            }
            __syncthreads();
        }
    }

    // -------- Final head: y_Tp1 = [d, c_t] . w_eff + b_eff --------
    if (wid < G) {
        int g = wid;
        float s = 0.f;
#pragma unroll
        for (int i = 0; i < 8; ++i) {
            int m = lane + 32 * i;
            s = fmaf(sD[m * GP + g], g_weff[m], s);
            s = fmaf(sCt[g * 256 + m], g_weff[256 + m], s);
        }
        s = wredsum(s);
        if (lane == 0 && base + g < CB) out[base + g] = s + g_beff[0];
    }
    // -------- beta output (last step's beta) --------
    for (int p = tid; p < G * CT; p += 512) {
        int g = p >> 6, tt = p & 63;
        if (base + g < CB)
            out[CB + (size_t)(base + g) * CT + tt] = sL[g * 64 + tt];
    }
}

// ---------------- launcher ----------------
extern "C" void kernel_launch(void* const* d_in, const int* in_sizes, int n_in,
                              void* d_out, int out_size)
{
    (void)in_sizes; (void)n_in; (void)out_size;
    const float* enc = (const float*)d_in[0];
    const float* y   = (const float*)d_in[1];
    const float* Wd  = (const float*)d_in[2];
    const float* Wdb = (const float*)d_in[3];
    const float* Ud  = (const float*)d_in[4];
    const float* vd  = (const float*)d_in[5];
    const float* wt  = (const float*)d_in[6];
    const float* wtb = (const float*)d_in[7];
    const float* Wy  = (const float*)d_in[8];
    const float* Wyb = (const float*)d_in[9];
    const float* vy  = (const float*)d_in[10];
    const float* vyb = (const float*)d_in[11];
    const float* Wih = (const float*)d_in[12];
    const float* Whh = (const float*)d_in[13];
    const float* bih = (const float*)d_in[14];
    const float* bhh = (const float*)d_in[15];
    float* out = (float*)d_out;

    cudaFuncSetAttribute(decoder_kernel,
                         cudaFuncAttributeMaxDynamicSharedMemorySize, SMEM_BYTES);

    prep_kernel<<<1031, 256>>>(Wd, Whh, Ud, bih, bhh, vy, Wy, Wyb, vyb);
    ue_kernel<<<8192, 256>>>(enc);
    decoder_kernel<<<NBLK, 512, SMEM_BYTES>>>(y, Wdb, vd, wt, wtb, Wih, out);
}

// round 4
// speedup vs baseline: 2.8426x; 1.2169x over previous
#include <cuda_runtime.h>
#include <cuda_fp16.h>

// Problem constants
#define CB   2048   // batch
#define CT   64     // T_enc == T_steps
#define CM   256    // M
#define CP   256    // P
#define G    14     // batches per block
#define GP   16     // padded G (float4-friendly row stride)
#define NBLK 147    // ceil(2048/14)

#define SMEM_FLOATS (26256)
#define SMEM_BYTES  (SMEM_FLOATS * 4)

typedef unsigned long long ull;

// ---------------- device scratch (no allocation allowed) ----------------
__device__ __align__(16) __half  g_UeH[(size_t)CB * CT * CM];   // fp16 Ue  (64 MB)
__device__ __align__(16) __half  g_encH[(size_t)CB * CT * CM];  // fp16 enc (64 MB)
__device__ __align__(16) float   g_we[(size_t)CB * CT];         // enc . w_tilda  (fp32)
__device__ __align__(16) __half2 g_WdH[256 * 256];    // [k2][n] = (Wd[n][2k2], Wd[n][2k2+1])
__device__ __align__(16) __half2 g_WhhH[128 * 1024];  // [k2][j] = (Whh[j][2k2], Whh[j][2k2+1])
__device__ __align__(16) float   g_UdT[256 * 256];    // [m][n] = U_d_w[n][m]
__device__ float g_bcomb[1024];                       // b_ih + b_hh
__device__ float g_weff[512];                         // v_y @ W_y  (folded head)
__device__ float g_beff[1];                           // v_y @ W_y_b + v_y_b

// ---------------- f32x2 packed-FMA helpers ----------------
__device__ __forceinline__ ull pack2(float lo, float hi) {
    ull r; asm("mov.b64 %0, {%1, %2};" : "=l"(r) : "f"(lo), "f"(hi)); return r;
}
__device__ __forceinline__ ull bcast2(float x) { return pack2(x, x); }
__device__ __forceinline__ ull fma2(ull a, ull b, ull c) {
    ull d; asm("fma.rn.f32x2 %0, %1, %2, %3;" : "=l"(d) : "l"(a), "l"(b), "l"(c)); return d;
}
__device__ __forceinline__ float2 unpack2(ull v) {
    float2 f; asm("mov.b64 {%0, %1}, %2;" : "=f"(f.x), "=f"(f.y) : "l"(v)); return f;
}

// ---------------- fast math helpers ----------------
__device__ __forceinline__ float fast_ex2(float x) {
    float y; asm("ex2.approx.f32 %0, %1;" : "=f"(y) : "f"(x)); return y;
}
__device__ __forceinline__ float fast_rcp(float x) {
    float y; asm("rcp.approx.f32 %0, %1;" : "=f"(y) : "f"(x)); return y;
}
// exact-ish tanh: 2 MUFU (used in LSTM recurrence path)
__device__ __forceinline__ float tanh_f(float x) {
    float e = fast_ex2(2.8853900817779268f * x);
    return fmaf(-2.f, fast_rcp(e + 1.f), 1.f);
}
// HW f16x2 tanh: 1 MUFU for 2 values (attention scores only)
__device__ __forceinline__ unsigned tanh_h2(unsigned x) {
    unsigned y; asm("tanh.approx.f16x2 %0, %1;" : "=r"(y) : "r"(x)); return y;
}
__device__ __forceinline__ float sigm_f(float x) {
    float e = fast_ex2(-1.4426950408889634f * x);
    return fast_rcp(1.f + e);
}
__device__ __forceinline__ float wredsum(float s) {
#pragma unroll
    for (int o = 16; o; o >>= 1) s += __shfl_xor_sync(0xffffffffu, s, o);
    return s;
}
__device__ __forceinline__ float wredmax(float s) {
#pragma unroll
    for (int o = 16; o; o >>= 1) s = fmaxf(s, __shfl_xor_sync(0xffffffffu, s, o));
    return s;
}

// load 14 floats as 7 packed f32x2 (row is 64B-aligned: GP*4 = 64)
#define LOADP7(dv, ptr) {                                                   \
    const ulonglong2* _r = (const ulonglong2*)(ptr);                        \
    ulonglong2 _a = _r[0], _b = _r[1], _c = _r[2];                          \
    ull _d = ((const ull*)(ptr))[6];                                        \
    dv[0]=_a.x; dv[1]=_a.y; dv[2]=_b.x; dv[3]=_b.y;                         \
    dv[4]=_c.x; dv[5]=_c.y; dv[6]=_d; }

// ---------------- prep: transposes + folded head ----------------
__global__ void prep_kernel(const float* __restrict__ Wd,
                            const float* __restrict__ Whh,
                            const float* __restrict__ Ud,
                            const float* __restrict__ bih,
                            const float* __restrict__ bhh,
                            const float* __restrict__ vy,
                            const float* __restrict__ Wy,
                            const float* __restrict__ Wyb,
                            const float* __restrict__ vyb)
{
    int i = blockIdx.x * blockDim.x + threadIdx.x;
    if (i < 65536) {   // W_d -> half2 pairs over k
        int k2 = i >> 8, n = i & 255;
        g_WdH[i] = __floats2half2_rn(Wd[n * 512 + 2 * k2], Wd[n * 512 + 2 * k2 + 1]);
        return;
    }
    i -= 65536;
    if (i < 131072) {  // W_hh -> half2 pairs over k
        int k2 = i >> 10, j = i & 1023;
        g_WhhH[i] = __floats2half2_rn(Whh[j * 256 + 2 * k2], Whh[j * 256 + 2 * k2 + 1]);
        return;
    }
    i -= 131072;
    if (i < 65536) { int m = i >> 8, n = i & 255; g_UdT[i] = Ud[n * 256 + m]; return; }
    i -= 65536;
    if (i < 1024) { g_bcomb[i] = bih[i] + bhh[i]; return; }
    i -= 1024;
    if (i < 512) {
        float s = 0.f;
        for (int j = 0; j < 256; ++j) s += vy[j] * Wy[j * 512 + i];
        g_weff[i] = s; return;
    }
    i -= 512;
    if (i == 0) {
        float s = 0.f;
        for (int j = 0; j < 256; ++j) s += vy[j] * Wyb[j];
        g_beff[0] = s + vyb[0];
    }
}

// ---------------- Ue = enc @ U_d^T (f32x2); fp16 enc copy; we = enc . w_tilda ----------------
__global__ __launch_bounds__(256) void ue_kernel(const float* __restrict__ enc,
                                                 const float* __restrict__ wt)
{
    __shared__ __align__(16) float Es[32][20];
    int bt0 = blockIdx.x * 16;
    int n = threadIdx.x;
    int lane = n & 31, wid = n >> 5;
    ull acc2[8];
#pragma unroll
    for (int j = 0; j < 8; ++j) acc2[j] = 0ull;

    for (int m0 = 0; m0 < 256; m0 += 32) {
        __syncthreads();
#pragma unroll
        for (int j = 0; j < 2; ++j) {
            int idx = n + j * 256;
            int r = idx >> 5, k = idx & 31;
            float v = enc[(size_t)(bt0 + r) * 256 + m0 + k];
            Es[k][r] = v;
            g_encH[(size_t)(bt0 + r) * 256 + m0 + k] = __float2half_rn(v);
        }
        __syncthreads();
#pragma unroll 8
        for (int k = 0; k < 32; ++k) {
            ull w2 = bcast2(g_UdT[(m0 + k) * 256 + n]);
            const ulonglong2* rp = (const ulonglong2*)&Es[k][0];
            ulonglong2 p0 = rp[0], p1 = rp[1], p2 = rp[2], p3 = rp[3];
            acc2[0] = fma2(w2, p0.x, acc2[0]);
            acc2[1] = fma2(w2, p0.y, acc2[1]);
            acc2[2] = fma2(w2, p1.x, acc2[2]);
            acc2[3] = fma2(w2, p1.y, acc2[3]);
            acc2[4] = fma2(w2, p2.x, acc2[4]);
            acc2[5] = fma2(w2, p2.y, acc2[5]);
            acc2[6] = fma2(w2, p3.x, acc2[6]);
            acc2[7] = fma2(w2, p3.y, acc2[7]);
        }
    }
#pragma unroll
    for (int j = 0; j < 8; ++j) {
        float2 f = unpack2(acc2[j]);
        g_UeH[(size_t)(bt0 + 2 * j)     * 256 + n] = __float2half_rn(f.x);
        g_UeH[(size_t)(bt0 + 2 * j + 1) * 256 + n] = __float2half_rn(f.y);
    }
    // we[bt] = enc[bt] . wt  (fp32, exact path) — warp per 2 rows
    for (int r = wid; r < 16; r += 8) {
        const float* ep = enc + (size_t)(bt0 + r) * 256;
        float s = 0.f;
#pragma unroll
        for (int i = 0; i < 8; ++i) s = fmaf(ep[lane + 32 * i], wt[lane + 32 * i], s);
        s = wredsum(s);
        if (lane == 0) g_we[bt0 + r] = s;
    }
}

// ---------------- persistent decoder: 147 blocks x 512 threads, G=14 batches/block ----------------
__global__ __launch_bounds__(512, 1) void decoder_kernel(
    const float* __restrict__ yin,
    const float* __restrict__ Wdb, const float* __restrict__ vd,
    const float* __restrict__ wt,  const float* __restrict__ wtb,
    const float* __restrict__ Wih, float* __restrict__ out)
{
    extern __shared__ __align__(16) float sm[];
    float* sD   = sm;            // [256][GP] hidden d
    float* sS   = sm + 4096;     // [256][GP] cell state
    float* sT1  = sm + 8192;     // [256][GP] temp: sigmoid(f)
    float* sT2  = sm + 12288;    // [256][GP] temp: tanh(c_new)
    float* sX1  = sm + 16384;    // [G][256]  x1 partial (half0's contribution)
    float* sCt  = sm + 19968;    // [G][256]  context c_t (final step only)
    float* sL   = sm + 23552;    // [G][64]   scores / beta
    float* sYt  = sm + 24448;    // [G]       y_tilda
    __half* sX1h = (__half*)(sm + 24464);  // [G][256] x1 in fp16

    const int tid  = threadIdx.x;
    const int lane = tid & 31;
    const int wid  = tid >> 5;
    const int half = tid >> 8;   // 0 or 1 (uniform per warp)
    const int n    = tid & 255;
    const int base = blockIdx.x * G;

    // per-lane cached vectors: vd packed f32x2 over 8 consecutive m's
    ull vd2[4];
#pragma unroll
    for (int j = 0; j < 4; ++j)
        vd2[j] = pack2(vd[lane * 8 + 2 * j], vd[lane * 8 + 2 * j + 1]);
    const float wt256 = wt[256];
    const float wtb0  = wtb[0];

    // zero state (covers sD and sS)
    for (int i = tid; i < 8192; i += 512) sD[i] = 0.f;
    __syncthreads();

    for (int t = 0; t < CT; ++t) {
        // -------- Phase A: x1 = W_d @ [d; s] + b_d  (f32x2, fp16 weights, prefetch d=8) --------
        {
            const float* src = half ? sS : sD;
            const __half2* wp = g_WdH + (half << 15) + n;  // (half*128)*256 + n
            ull acc[7];
#pragma unroll
            for (int j = 0; j < 7; ++j) acc[j] = 0ull;

            __half2 wbuf[8];
#pragma unroll
            for (int j = 0; j < 8; ++j) wbuf[j] = wp[j << 8];

            auto abody = [&](int k2, bool pf) {
                float2 wf = __half22float2(wbuf[k2 & 7]);
                if (pf) wbuf[k2 & 7] = wp[(k2 + 8) << 8];
                ull w0 = bcast2(wf.x), w1 = bcast2(wf.y);
                ull dv[7];
                LOADP7(dv, src + (2 * k2) * GP);
#pragma unroll
                for (int j = 0; j < 7; ++j) acc[j] = fma2(w0, dv[j], acc[j]);
                LOADP7(dv, src + (2 * k2 + 1) * GP);
#pragma unroll
                for (int j = 0; j < 7; ++j) acc[j] = fma2(w1, dv[j], acc[j]);
            };
#pragma unroll 8
            for (int k2 = 0; k2 < 120; ++k2) abody(k2, true);
#pragma unroll
            for (int k2 = 120; k2 < 128; ++k2) abody(k2, false);

            float av[G];
#pragma unroll
            for (int j = 0; j < 7; ++j) {
                float2 f = unpack2(acc[j]);
                av[2 * j] = f.x; av[2 * j + 1] = f.y;
            }
            if (half == 0) {
#pragma unroll
                for (int g = 0; g < G; ++g) sX1[g * 256 + n] = av[g];
            }
            __syncthreads();
            if (half == 1) {
                float bb = Wdb[n];
#pragma unroll
                for (int g = 0; g < G; ++g)
                    sX1h[g * 256 + n] = __float2half_rn(sX1[g * 256 + n] + av[g] + bb);
            }
            __syncthreads();
        }

        // -------- Phase B: attention scores, 4-way interleave, fp16 front-end --------
        for (int p0 = wid; p0 < G * CT; p0 += 64) {
            uint4 u[4], x[4];
#pragma unroll
            for (int j = 0; j < 4; ++j) {
                int p = p0 + 16 * j;
                int b = min(base + (p >> 6), CB - 1);
                u[j] = *((const uint4*)(g_UeH + (((size_t)b * CT + (p & 63)) << 8)) + lane);
                x[j] = *((const uint4*)(sX1h + ((p >> 6) << 8)) + lane);
            }
            float sres[4];
#pragma unroll
            for (int j = 0; j < 4; ++j) {
                const __half2* uh = (const __half2*)&u[j];
                const __half2* xh = (const __half2*)&x[j];
                __half2 s0 = __hadd2(uh[0], xh[0]);
                __half2 s1 = __hadd2(uh[1], xh[1]);
                __half2 s2 = __hadd2(uh[2], xh[2]);
                __half2 s3 = __hadd2(uh[3], xh[3]);
                unsigned z0 = tanh_h2(*(unsigned*)&s0);
                unsigned z1 = tanh_h2(*(unsigned*)&s1);
                unsigned z2 = tanh_h2(*(unsigned*)&s2);
                unsigned z3 = tanh_h2(*(unsigned*)&s3);
                float2 f0 = __half22float2(*(__half2*)&z0);
                float2 f1 = __half22float2(*(__half2*)&z1);
                float2 f2 = __half22float2(*(__half2*)&z2);
                float2 f3 = __half22float2(*(__half2*)&z3);
                ull acc = 0ull;
                acc = fma2(pack2(f0.x, f0.y), vd2[0], acc);
                acc = fma2(pack2(f1.x, f1.y), vd2[1], acc);
                acc = fma2(pack2(f2.x, f2.y), vd2[2], acc);
                acc = fma2(pack2(f3.x, f3.y), vd2[3], acc);
                float2 f = unpack2(acc);
                sres[j] = f.x + f.y;
            }
#pragma unroll
            for (int o = 16; o; o >>= 1) {
#pragma unroll
                for (int j = 0; j < 4; ++j)
                    sres[j] += __shfl_xor_sync(0xffffffffu, sres[j], o);
            }
            if (lane == 0) {
#pragma unroll
                for (int j = 0; j < 4; ++j) sL[p0 + 16 * j] = sres[j];
            }
        }
        __syncthreads();

        // -------- Phase B2: softmax + fused y_tilda (y_t = (sum e*we)/(sum e)) --------
        if (wid < G) {
            int g = wid;
            int b = min(base + g, CB - 1);
            float l0 = sL[g * 64 + lane], l1 = sL[g * 64 + 32 + lane];
            float mx = wredmax(fmaxf(l0, l1));
            float e0 = fast_ex2((l0 - mx) * 1.4426950408889634f);
            float e1 = fast_ex2((l1 - mx) * 1.4426950408889634f);
            float w0 = g_we[b * CT + lane], w1 = g_we[b * CT + 32 + lane];
            float ps = e0 + e1;
            float pw = fmaf(e0, w0, e1 * w1);
#pragma unroll
            for (int o = 16; o; o >>= 1) {
                ps += __shfl_xor_sync(0xffffffffu, ps, o);
                pw += __shfl_xor_sync(0xffffffffu, pw, o);
            }
            float inv = fast_rcp(ps);
            inv = inv * (2.f - ps * inv);   // NR refine
            sL[g * 64 + lane]      = e0 * inv;
            sL[g * 64 + 32 + lane] = e1 * inv;
            if (lane == 0) {
                float yt = yin[b * CT + t];
                sYt[g] = fmaf(pw, inv, fmaf(yt, wt256, wtb0));
            }
        }
        __syncthreads();

        // -------- Phase E: LSTM cell (f32x2, fp16 weights, prefetch d=4 x2 streams) --------
        {
            const int jA = n + (half << 8);  // half0: i-gate, half1: f-gate
            const int jB = jA + 512;         // half0: g-gate, half1: o-gate
            ull aA[7], aB[7];
#pragma unroll
            for (int j = 0; j < 7; ++j) { aA[j] = 0ull; aB[j] = 0ull; }
            const __half2* wA = g_WhhH + jA;
            const __half2* wB = g_WhhH + jB;

            __half2 wbA[4], wbB[4];
#pragma unroll
            for (int j = 0; j < 4; ++j) { wbA[j] = wA[j << 10]; wbB[j] = wB[j << 10]; }

            auto ebody = [&](int k2, bool pf) {
                float2 fA = __half22float2(wbA[k2 & 3]);
                float2 fB = __half22float2(wbB[k2 & 3]);
                if (pf) { wbA[k2 & 3] = wA[(k2 + 4) << 10]; wbB[k2 & 3] = wB[(k2 + 4) << 10]; }
                ull a0 = bcast2(fA.x), a1 = bcast2(fA.y);
                ull b0 = bcast2(fB.x), b1 = bcast2(fB.y);
                ull dv[7];
                LOADP7(dv, sD + (2 * k2) * GP);
#pragma unroll
                for (int j = 0; j < 7; ++j) {
                    aA[j] = fma2(a0, dv[j], aA[j]);
                    aB[j] = fma2(b0, dv[j], aB[j]);
                }
                LOADP7(dv, sD + (2 * k2 + 1) * GP);
#pragma unroll
                for (int j = 0; j < 7; ++j) {
                    aA[j] = fma2(a1, dv[j], aA[j]);
                    aB[j] = fma2(b1, dv[j], aB[j]);
                }
            };
#pragma unroll 4
            for (int k2 = 0; k2 < 124; ++k2) ebody(k2, true);
#pragma unroll
            for (int k2 = 124; k2 < 128; ++k2) ebody(k2, false);

            float accA[G], accB[G];
#pragma unroll
            for (int j = 0; j < 7; ++j) {
                float2 fa = unpack2(aA[j]), fb = unpack2(aB[j]);
                accA[2 * j] = fa.x; accA[2 * j + 1] = fa.y;
                accB[2 * j] = fb.x; accB[2 * j + 1] = fb.y;
            }
            float bA = g_bcomb[jA], bB = g_bcomb[jB];
            float wiA = Wih[jA],   wiB = Wih[jB];
            float vA[G], vB[G];
#pragma unroll
            for (int g = 0; g < G; ++g) {
                float yt = sYt[g];
                float gA = accA[g] + bA + yt * wiA;
                float gB = accB[g] + bB + yt * wiB;
                vA[g] = sigm_f(gA);                              // sig(i) or sig(f)
                vB[g] = half ? sigm_f(gB) : tanh_f(gB);          // sig(o) or tanh(g)
            }
            if (half == 1) {
#pragma unroll
                for (int g = 0; g < G; ++g) sT1[n * GP + g] = vA[g];   // sig(f)
            }
            __syncthreads();
            if (half == 0) {
#pragma unroll
                for (int g = 0; g < G; ++g) {
                    float cn = fmaf(sT1[n * GP + g], sS[n * GP + g], vA[g] * vB[g]);
                    sS[n * GP + g]  = cn;
                    sT2[n * GP + g] = tanh_f(cn);
                }
            }
            __syncthreads();
            if (half == 1) {
#pragma unroll
                for (int g = 0; g < G; ++g)
                    sD[n * GP + g] = vB[g] * sT2[n * GP + g];     // h = sig(o)*tanh(c)
            }
            __syncthreads();
        }
    }

    // -------- Phase C (once): c_t = beta @ enc for final step --------
    if (wid < G) {
        int g = wid;
        int b = min(base + g, CB - 1);
        const uint4* ep = (const uint4*)(g_encH + ((size_t)b * CT << 8)) + lane;
        ull a0 = 0ull, a1 = 0ull, a2 = 0ull, a3 = 0ull;
        for (int t0 = 0; t0 < 64; t0 += 8) {
            uint4 uu[8];
#pragma unroll
            for (int j = 0; j < 8; ++j) uu[j] = ep[(t0 + j) << 5];
#pragma unroll
            for (int j = 0; j < 8; ++j) {
                ull b2 = bcast2(sL[g * 64 + t0 + j]);
                const __half2* uh = (const __half2*)&uu[j];
                float2 e0 = __half22float2(uh[0]), e1 = __half22float2(uh[1]);
                float2 e2 = __half22float2(uh[2]), e3 = __half22float2(uh[3]);
                a0 = fma2(b2, pack2(e0.x, e0.y), a0);
                a1 = fma2(b2, pack2(e1.x, e1.y), a1);
                a2 = fma2(b2, pack2(e2.x, e2.y), a2);
                a3 = fma2(b2, pack2(e3.x, e3.y), a3);
            }
        }
        float* cp = sCt + g * 256 + lane * 8;
        float2 f0 = unpack2(a0), f1 = unpack2(a1);
        float2 f2 = unpack2(a2), f3 = unpack2(a3);
        ((float4*)cp)[0] = make_float4(f0.x, f0.y, f1.x, f1.y);
        ((float4*)cp)[1] = make_float4(f2.x, f2.y, f3.x, f3.y);
    }
    __syncthreads();

    // -------- Final head: y_Tp1 = [d, c_t] . w_eff + b_eff --------
    if (wid < G) {
        int g = wid;
        float s = 0.f;
#pragma unroll
        for (int i = 0; i < 8; ++i) {
            int m = lane + 32 * i;
            s = fmaf(sD[m * GP + g], g_weff[m], s);
            s = fmaf(sCt[g * 256 + m], g_weff[256 + m], s);
        }
        s = wredsum(s);
        if (lane == 0 && base + g < CB) out[base + g] = s + g_beff[0];
    }
    // -------- beta output (last step's beta) --------
    for (int p = tid; p < G * CT; p += 512) {
        int g = p >> 6, tt = p & 63;
        if (base + g < CB)
            out[CB + (size_t)(base + g) * CT + tt] = sL[g * 64 + tt];
    }
}

// ---------------- launcher ----------------
extern "C" void kernel_launch(void* const* d_in, const int* in_sizes, int n_in,
                              void* d_out, int out_size)
{
    (void)in_sizes; (void)n_in; (void)out_size;
    const float* enc = (const float*)d_in[0];
    const float* y   = (const float*)d_in[1];
    const float* Wd  = (const float*)d_in[2];
    const float* Wdb = (const float*)d_in[3];
    const float* Ud  = (const float*)d_in[4];
    const float* vd  = (const float*)d_in[5];
    const float* wt  = (const float*)d_in[6];
    const float* wtb = (const float*)d_in[7];
    const float* Wy  = (const float*)d_in[8];
    const float* Wyb = (const float*)d_in[9];
    const float* vy  = (const float*)d_in[10];
    const float* vyb = (const float*)d_in[11];
    const float* Wih = (const float*)d_in[12];
    const float* Whh = (const float*)d_in[13];
    const float* bih = (const float*)d_in[14];
    const float* bhh = (const float*)d_in[15];
    float* out = (float*)d_out;

    cudaFuncSetAttribute(decoder_kernel,
                         cudaFuncAttributeMaxDynamicSharedMemorySize, SMEM_BYTES);

    prep_kernel<<<1031, 256>>>(Wd, Whh, Ud, bih, bhh, vy, Wy, Wyb, vyb);
    ue_kernel<<<8192, 256>>>(enc, wt);
    decoder_kernel<<<NBLK, 512, SMEM_BYTES>>>(y, Wdb, vd, wt, wtb, Wih, out);
}

// round 6
// speedup vs baseline: 5.8376x; 2.0537x over previous
#include <cuda_runtime.h>
#include <cuda_fp16.h>
#include <cstdint>

// Problem constants
#define CB   2048
#define CT   64
#define CM   256
#define CP   256
#define G    14
#define GP   20      // padded batch stride (floats) — 4-way-conflict-free
#define NBLK 147
#define DSS  520     // sDSh row stride in halves ([d(256) | c(256)] + pad)

// smem layout (float offsets)
#define OFF_SGATE 0        // [1024][GP] fp32 gates        = 20480
#define OFF_SD    20480    // [256][GP] fp32 hidden d      = 5120
#define OFF_SS    25600    // [256][GP] fp32 cell c        = 5120
#define OFF_SDSH  30720    // [16][DSS] fp16 [d|c]         = 4160 floats
#define OFF_SX1H  34880    // [16][256] fp16 x1            = 2048 floats
#define OFF_SCT   36928    // [14][256] fp32 context       = 3584
#define OFF_SL    40512    // [14][64] scores/beta         = 896
#define OFF_SYT   41408    // [16] y_tilda
#define SMEM_FLOATS 41424
#define SMEM_BYTES  (SMEM_FLOATS * 4)

typedef unsigned long long ull;

// ---------------- device scratch ----------------
__device__ __align__(16) __half  g_UeH[(size_t)CB * CT * CM];   // fp16 Ue
__device__ __align__(16) __half  g_encH[(size_t)CB * CT * CM];  // fp16 enc
__device__ __align__(16) float   g_we[(size_t)CB * CT];         // enc . w_tilda
__device__ __align__(16) uint4   g_WdF[16 * 32 * 32];           // Wd  fragments [w][kt][lane]
__device__ __align__(16) uint4   g_WhhF[16 * 16 * 4 * 32];      // Whh fragments [w][kt][mt][lane]
__device__ __align__(16) float   g_UdT[256 * 256];
__device__ float g_bcomb[1024];
__device__ float g_weff[512];
__device__ float g_beff[1];

// ---------------- helpers ----------------
__device__ __forceinline__ ull pack2(float lo, float hi) {
    ull r; asm("mov.b64 %0, {%1, %2};" : "=l"(r) : "f"(lo), "f"(hi)); return r;
}
__device__ __forceinline__ ull bcast2(float x) { return pack2(x, x); }
__device__ __forceinline__ ull fma2(ull a, ull b, ull c) {
    ull d; asm("fma.rn.f32x2 %0, %1, %2, %3;" : "=l"(d) : "l"(a), "l"(b), "l"(c)); return d;
}
__device__ __forceinline__ float2 unpack2(ull v) {
    float2 f; asm("mov.b64 {%0, %1}, %2;" : "=f"(f.x), "=f"(f.y) : "l"(v)); return f;
}
__device__ __forceinline__ float fast_ex2(float x) {
    float y; asm("ex2.approx.f32 %0, %1;" : "=f"(y) : "f"(x)); return y;
}
__device__ __forceinline__ float fast_rcp(float x) {
    float y; asm("rcp.approx.f32 %0, %1;" : "=f"(y) : "f"(x)); return y;
}
__device__ __forceinline__ float tanh_f(float x) {
    float e = fast_ex2(2.8853900817779268f * x);
    return fmaf(-2.f, fast_rcp(e + 1.f), 1.f);
}
__device__ __forceinline__ unsigned tanh_h2(unsigned x) {
    unsigned y; asm("tanh.approx.f16x2 %0, %1;" : "=r"(y) : "r"(x)); return y;
}
__device__ __forceinline__ float sigm_f(float x) {
    float e = fast_ex2(-1.4426950408889634f * x);
    return fast_rcp(1.f + e);
}
__device__ __forceinline__ float wredsum(float s) {
#pragma unroll
    for (int o = 16; o; o >>= 1) s += __shfl_xor_sync(0xffffffffu, s, o);
    return s;
}
__device__ __forceinline__ float wredmax(float s) {
#pragma unroll
    for (int o = 16; o; o >>= 1) s = fmaxf(s, __shfl_xor_sync(0xffffffffu, s, o));
    return s;
}
// m16n8k16 row.col f32.f16.f16.f32
__device__ __forceinline__ void mma16816(float* c, uint4 A, uint32_t b0, uint32_t b1) {
    asm volatile("mma.sync.aligned.m16n8k16.row.col.f32.f16.f16.f32 "
        "{%0,%1,%2,%3}, {%4,%5,%6,%7}, {%8,%9}, {%0,%1,%2,%3};"
        : "+f"(c[0]), "+f"(c[1]), "+f"(c[2]), "+f"(c[3])
        : "r"(A.x), "r"(A.y), "r"(A.z), "r"(A.w), "r"(b0), "r"(b1));
}

// ---------------- prep: weight fragments + transposes + folded head ----------------
__global__ void prep_kernel(const float* __restrict__ Wd,
                            const float* __restrict__ Whh,
                            const float* __restrict__ Ud,
                            const float* __restrict__ bih,
                            const float* __restrict__ bhh,
                            const float* __restrict__ vy,
                            const float* __restrict__ Wy,
                            const float* __restrict__ Wyb,
                            const float* __restrict__ vyb)
{
    int i = blockIdx.x * blockDim.x + threadIdx.x;
    if (i < 16384) {   // Wd fragments: [w(16)][kt(32)][lane(32)]
        int lane = i & 31, kt = (i >> 5) & 31, w = i >> 10;
        int j0 = w * 16 + (lane >> 2);
        int k0 = kt * 16 + (lane & 3) * 2;
        __half2 a = __floats2half2_rn(Wd[j0 * 512 + k0],       Wd[j0 * 512 + k0 + 1]);
        __half2 b = __floats2half2_rn(Wd[(j0 + 8) * 512 + k0], Wd[(j0 + 8) * 512 + k0 + 1]);
        __half2 c = __floats2half2_rn(Wd[j0 * 512 + k0 + 8],   Wd[j0 * 512 + k0 + 9]);
        __half2 d = __floats2half2_rn(Wd[(j0 + 8) * 512 + k0 + 8], Wd[(j0 + 8) * 512 + k0 + 9]);
        uint4 v;
        v.x = *(uint32_t*)&a; v.y = *(uint32_t*)&b; v.z = *(uint32_t*)&c; v.w = *(uint32_t*)&d;
        g_WdF[i] = v;
        return;
    }
    i -= 16384;
    if (i < 32768) {   // Whh fragments: [w(16)][kt(16)][mt(4)][lane(32)]
        int lane = i & 31, mt = (i >> 5) & 3, kt = (i >> 7) & 15, w = i >> 11;
        int j0 = w * 64 + mt * 16 + (lane >> 2);
        int k0 = kt * 16 + (lane & 3) * 2;
        __half2 a = __floats2half2_rn(Whh[j0 * 256 + k0],       Whh[j0 * 256 + k0 + 1]);
        __half2 b = __floats2half2_rn(Whh[(j0 + 8) * 256 + k0], Whh[(j0 + 8) * 256 + k0 + 1]);
        __half2 c = __floats2half2_rn(Whh[j0 * 256 + k0 + 8],   Whh[j0 * 256 + k0 + 9]);
        __half2 d = __floats2half2_rn(Whh[(j0 + 8) * 256 + k0 + 8], Whh[(j0 + 8) * 256 + k0 + 9]);
        uint4 v;
        v.x = *(uint32_t*)&a; v.y = *(uint32_t*)&b; v.z = *(uint32_t*)&c; v.w = *(uint32_t*)&d;
        g_WhhF[i] = v;
        return;
    }
    i -= 32768;
    if (i < 65536) { int m = i >> 8, n = i & 255; g_UdT[i] = Ud[n * 256 + m]; return; }
    i -= 65536;
    if (i < 1024) { g_bcomb[i] = bih[i] + bhh[i]; return; }
    i -= 1024;
    if (i < 512) {
        float s = 0.f;
        for (int j = 0; j < 256; ++j) s += vy[j] * Wy[j * 512 + i];
        g_weff[i] = s; return;
    }
    i -= 512;
    if (i == 0) {
        float s = 0.f;
        for (int j = 0; j < 256; ++j) s += vy[j] * Wyb[j];
        g_beff[0] = s + vyb[0];
    }
}

// ---------------- Ue = enc @ U_d^T ; fp16 enc copy ; we = enc . w_tilda ----------------
__global__ __launch_bounds__(256) void ue_kernel(const float* __restrict__ enc,
                                                 const float* __restrict__ wt)
{
    __shared__ __align__(16) float Es[32][20];
    int bt0 = blockIdx.x * 16;
    int n = threadIdx.x;
    int lane = n & 31, wid = n >> 5;
    ull acc2[8];
#pragma unroll
    for (int j = 0; j < 8; ++j) acc2[j] = 0ull;

    for (int m0 = 0; m0 < 256; m0 += 32) {
        __syncthreads();
#pragma unroll
        for (int j = 0; j < 2; ++j) {
            int idx = n + j * 256;
            int r = idx >> 5, k = idx & 31;
            float v = enc[(size_t)(bt0 + r) * 256 + m0 + k];
            Es[k][r] = v;
            g_encH[(size_t)(bt0 + r) * 256 + m0 + k] = __float2half_rn(v);
        }
        __syncthreads();
#pragma unroll 8
        for (int k = 0; k < 32; ++k) {
            ull w2 = bcast2(g_UdT[(m0 + k) * 256 + n]);
            const ulonglong2* rp = (const ulonglong2*)&Es[k][0];
            ulonglong2 p0 = rp[0], p1 = rp[1], p2 = rp[2], p3 = rp[3];
            acc2[0] = fma2(w2, p0.x, acc2[0]);
            acc2[1] = fma2(w2, p0.y, acc2[1]);
            acc2[2] = fma2(w2, p1.x, acc2[2]);
            acc2[3] = fma2(w2, p1.y, acc2[3]);
            acc2[4] = fma2(w2, p2.x, acc2[4]);
            acc2[5] = fma2(w2, p2.y, acc2[5]);
            acc2[6] = fma2(w2, p3.x, acc2[6]);
            acc2[7] = fma2(w2, p3.y, acc2[7]);
        }
    }
#pragma unroll
    for (int j = 0; j < 8; ++j) {
        float2 f = unpack2(acc2[j]);
        g_UeH[(size_t)(bt0 + 2 * j)     * 256 + n] = __float2half_rn(f.x);
        g_UeH[(size_t)(bt0 + 2 * j + 1) * 256 + n] = __float2half_rn(f.y);
    }
    for (int r = wid; r < 16; r += 8) {
        const float* ep = enc + (size_t)(bt0 + r) * 256;
        float s = 0.f;
#pragma unroll
        for (int i = 0; i < 8; ++i) s = fmaf(ep[lane + 32 * i], wt[lane + 32 * i], s);
        s = wredsum(s);
        if (lane == 0) g_we[bt0 + r] = s;
    }
}

// ---------------- persistent decoder ----------------
__global__ __launch_bounds__(512, 1) void decoder_kernel(
    const float* __restrict__ yin,
    const float* __restrict__ Wdb, const float* __restrict__ vd,
    const float* __restrict__ wt,  const float* __restrict__ wtb,
    const float* __restrict__ Wih, float* __restrict__ out)
{
    extern __shared__ __align__(16) float sm[];
    float*  sGate = sm + OFF_SGATE;
    float*  sD    = sm + OFF_SD;
    float*  sS    = sm + OFF_SS;
    __half* sDSh  = (__half*)(sm + OFF_SDSH);
    __half* sX1h  = (__half*)(sm + OFF_SX1H);
    float*  sCt   = sm + OFF_SCT;
    float*  sL    = sm + OFF_SL;
    float*  sYt   = sm + OFF_SYT;

    const int tid  = threadIdx.x;
    const int lane = tid & 31;
    const int wid  = tid >> 5;
    const int half = tid >> 8;
    const int n    = tid & 255;
    const int base = blockIdx.x * G;

    // zero state: sD + sS (fp32) and sDSh (fp16) and sYt
    for (int i = tid; i < 10240; i += 512) sD[i] = 0.f;    // covers sD & sS
    for (int i = tid; i < 4160; i += 512) ((float*)sDSh)[i] = 0.f;
    if (tid < 16) sYt[tid] = 0.f;

    // cached per-lane vectors
    ull vd2[4];
#pragma unroll
    for (int j = 0; j < 4; ++j)
        vd2[j] = pack2(vd[lane * 8 + 2 * j], vd[lane * 8 + 2 * j + 1]);
    const float wt256 = wt[256];
    const float wtb0  = wtb[0];

    // per-thread pointwise constants (unit n)
    const float bI = g_bcomb[n],       wI = Wih[n];
    const float bF = g_bcomb[256 + n], wF = Wih[256 + n];
    const float bG = g_bcomb[512 + n], wG = Wih[512 + n];
    const float bO = g_bcomb[768 + n], wO = Wih[768 + n];

    // MMA geometry
    const int n0   = lane >> 2;          // B/C col within 8-tile
    const int koff = (lane & 3) * 2;
    const int r0A  = wid * 16 + n0;      // Phase-A output row
    const float bb0 = Wdb[r0A], bb1 = Wdb[r0A + 8];
    const uint4* afA = g_WdF  + (wid << 10) + lane;   // [w][kt][lane]
    const uint4* afE = g_WhhF + (wid << 11) + lane;   // [w][kt][mt][lane]

    __syncthreads();

    for (int t = 0; t < CT; ++t) {
        // ---- MMA-A: x1[256x16] = Wd[256x512] @ [d;c][512x16] ----
        {
            float c0[4] = {0, 0, 0, 0}, c1[4] = {0, 0, 0, 0};
#pragma unroll 4
            for (int kt = 0; kt < 32; ++kt) {
                uint4 A = afA[kt << 5];
                int k0 = (kt << 4) + koff;
                uint32_t b00 = *(const uint32_t*)(sDSh + n0 * DSS + k0);
                uint32_t b01 = *(const uint32_t*)(sDSh + n0 * DSS + k0 + 8);
                uint32_t b10 = *(const uint32_t*)(sDSh + (8 + n0) * DSS + k0);
                uint32_t b11 = *(const uint32_t*)(sDSh + (8 + n0) * DSS + k0 + 8);
                mma16816(c0, A, b00, b01);
                mma16816(c1, A, b10, b11);
            }
            int g0 = (lane & 3) * 2;
            sX1h[g0 * 256 + r0A]           = __float2half_rn(c0[0] + bb0);
            sX1h[(g0 + 1) * 256 + r0A]     = __float2half_rn(c0[1] + bb0);
            sX1h[g0 * 256 + r0A + 8]       = __float2half_rn(c0[2] + bb1);
            sX1h[(g0 + 1) * 256 + r0A + 8] = __float2half_rn(c0[3] + bb1);
            sX1h[(g0 + 8) * 256 + r0A]           = __float2half_rn(c1[0] + bb0);
            sX1h[(g0 + 9) * 256 + r0A]           = __float2half_rn(c1[1] + bb0);
            sX1h[(g0 + 8) * 256 + r0A + 8]       = __float2half_rn(c1[2] + bb1);
            sX1h[(g0 + 9) * 256 + r0A + 8]       = __float2half_rn(c1[3] + bb1);
        }

        // ---- MMA-E: gates[1024x16] = Whh[1024x256] @ d[256x16] ----
        {
            float c[4][2][4];
#pragma unroll
            for (int mt = 0; mt < 4; ++mt)
#pragma unroll
                for (int nt = 0; nt < 2; ++nt)
#pragma unroll
                    for (int q = 0; q < 4; ++q) c[mt][nt][q] = 0.f;
#pragma unroll 2
            for (int kt = 0; kt < 16; ++kt) {
                int k0 = (kt << 4) + koff;
                uint32_t b00 = *(const uint32_t*)(sDSh + n0 * DSS + k0);
                uint32_t b01 = *(const uint32_t*)(sDSh + n0 * DSS + k0 + 8);
                uint32_t b10 = *(const uint32_t*)(sDSh + (8 + n0) * DSS + k0);
                uint32_t b11 = *(const uint32_t*)(sDSh + (8 + n0) * DSS + k0 + 8);
#pragma unroll
                for (int mt = 0; mt < 4; ++mt) {
                    uint4 A = afE[((kt << 2) + mt) << 5];
                    mma16816(c[mt][0], A, b00, b01);
                    mma16816(c[mt][1], A, b10, b11);
                }
            }
            int g0 = (lane & 3) * 2;
#pragma unroll
            for (int mt = 0; mt < 4; ++mt) {
                int r = wid * 64 + mt * 16 + n0;
#pragma unroll
                for (int nt = 0; nt < 2; ++nt) {
                    int g = nt * 8 + g0;
                    *(float2*)&sGate[r * GP + g]       = make_float2(c[mt][nt][0], c[mt][nt][1]);
                    *(float2*)&sGate[(r + 8) * GP + g] = make_float2(c[mt][nt][2], c[mt][nt][3]);
                }
            }
        }
        __syncthreads();

        // ---- Phase B: attention scores (fp16, 4-way interleave) ----
        for (int p0 = wid; p0 < G * CT; p0 += 64) {
            uint4 u[4], x[4];
#pragma unroll
            for (int j = 0; j < 4; ++j) {
                int p = p0 + 16 * j;
                int b = min(base + (p >> 6), CB - 1);
                u[j] = *((const uint4*)(g_UeH + (((size_t)b * CT + (p & 63)) << 8)) + lane);
                x[j] = *((const uint4*)(sX1h + ((p >> 6) << 8)) + lane);
            }
            float sres[4];
#pragma unroll
            for (int j = 0; j < 4; ++j) {
                const __half2* uh = (const __half2*)&u[j];
                const __half2* xh = (const __half2*)&x[j];
                __half2 s0 = __hadd2(uh[0], xh[0]);
                __half2 s1 = __hadd2(uh[1], xh[1]);
                __half2 s2 = __hadd2(uh[2], xh[2]);
                __half2 s3 = __hadd2(uh[3], xh[3]);
                unsigned z0 = tanh_h2(*(unsigned*)&s0);
                unsigned z1 = tanh_h2(*(unsigned*)&s1);
                unsigned z2 = tanh_h2(*(unsigned*)&s2);
                unsigned z3 = tanh_h2(*(unsigned*)&s3);
                float2 f0 = __half22float2(*(__half2*)&z0);
                float2 f1 = __half22float2(*(__half2*)&z1);
                float2 f2 = __half22float2(*(__half2*)&z2);
                float2 f3 = __half22float2(*(__half2*)&z3);
                ull acc = 0ull;
                acc = fma2(pack2(f0.x, f0.y), vd2[0], acc);
                acc = fma2(pack2(f1.x, f1.y), vd2[1], acc);
                acc = fma2(pack2(f2.x, f2.y), vd2[2], acc);
                acc = fma2(pack2(f3.x, f3.y), vd2[3], acc);
                float2 f = unpack2(acc);
                sres[j] = f.x + f.y;
            }
#pragma unroll
            for (int o = 16; o; o >>= 1) {
#pragma unroll
                for (int j = 0; j < 4; ++j)
                    sres[j] += __shfl_xor_sync(0xffffffffu, sres[j], o);
            }
            if (lane == 0) {
#pragma unroll
                for (int j = 0; j < 4; ++j) sL[p0 + 16 * j] = sres[j];
            }
        }
        __syncthreads();

        // ---- B2: softmax + fused y_tilda ----
        if (wid < G) {
            int g = wid;
            int b = min(base + g, CB - 1);
            float l0 = sL[g * 64 + lane], l1 = sL[g * 64 + 32 + lane];
            float mx = wredmax(fmaxf(l0, l1));
            float e0 = fast_ex2((l0 - mx) * 1.4426950408889634f);
            float e1 = fast_ex2((l1 - mx) * 1.4426950408889634f);
            float w0 = g_we[b * CT + lane], w1 = g_we[b * CT + 32 + lane];
            float ps = e0 + e1;
            float pw = fmaf(e0, w0, e1 * w1);
#pragma unroll
            for (int o = 16; o; o >>= 1) {
                ps += __shfl_xor_sync(0xffffffffu, ps, o);
                pw += __shfl_xor_sync(0xffffffffu, pw, o);
            }
            float inv = fast_rcp(ps);
            inv = inv * (2.f - ps * inv);
            sL[g * 64 + lane]      = e0 * inv;
            sL[g * 64 + 32 + lane] = e1 * inv;
            if (lane == 0) {
                float yt = yin[b * CT + t];
                sYt[g] = fmaf(pw, inv, fmaf(yt, wt256, wtb0));
            }
        }
        __syncthreads();

        // ---- E-final: LSTM pointwise (thread = unit n; half picks batch range) ----
        {
#pragma unroll
            for (int gi = 0; gi < 7; ++gi) {
                int g = half * 7 + gi;
                float yt = sYt[g];
                float iv = sGate[n * GP + g]         + bI + yt * wI;
                float fv = sGate[(256 + n) * GP + g] + bF + yt * wF;
                float gv = sGate[(512 + n) * GP + g] + bG + yt * wG;
                float ov = sGate[(768 + n) * GP + g] + bO + yt * wO;
                float c_old = sS[n * GP + g];
                float cn = fmaf(sigm_f(fv), c_old, sigm_f(iv) * tanh_f(gv));
                sS[n * GP + g] = cn;
                float h = sigm_f(ov) * tanh_f(cn);
                sD[n * GP + g] = h;
                sDSh[g * DSS + n]       = __float2half_rn(h);
                sDSh[g * DSS + 256 + n] = __float2half_rn(cn);
            }
        }
        __syncthreads();
    }

    // ---- Phase C (once): c_t = beta @ enc ----
    if (wid < G) {
        int g = wid;
        int b = min(base + g, CB - 1);
        const uint4* ep = (const uint4*)(g_encH + ((size_t)b * CT << 8)) + lane;
        ull a0 = 0ull, a1 = 0ull, a2 = 0ull, a3 = 0ull;
        for (int t0 = 0; t0 < 64; t0 += 8) {
            uint4 uu[8];
#pragma unroll
            for (int j = 0; j < 8; ++j) uu[j] = ep[(t0 + j) << 5];
#pragma unroll
            for (int j = 0; j < 8; ++j) {
                ull b2 = bcast2(sL[g * 64 + t0 + j]);
                const __half2* uh = (const __half2*)&uu[j];
                float2 e0 = __half22float2(uh[0]), e1 = __half22float2(uh[1]);
                float2 e2 = __half22float2(uh[2]), e3 = __half22float2(uh[3]);
                a0 = fma2(b2, pack2(e0.x, e0.y), a0);
                a1 = fma2(b2, pack2(e1.x, e1.y), a1);
                a2 = fma2(b2, pack2(e2.x, e2.y), a2);
                a3 = fma2(b2, pack2(e3.x, e3.y), a3);
            }
        }
        float* cp = sCt + g * 256 + lane * 8;
        float2 f0 = unpack2(a0), f1 = unpack2(a1);
        float2 f2 = unpack2(a2), f3 = unpack2(a3);
        ((float4*)cp)[0] = make_float4(f0.x, f0.y, f1.x, f1.y);
        ((float4*)cp)[1] = make_float4(f2.x, f2.y, f3.x, f3.y);
    }
    __syncthreads();

    // ---- Final head ----
    if (wid < G) {
        int g = wid;
        float s = 0.f;
#pragma unroll
        for (int i = 0; i < 8; ++i) {
            int m = lane + 32 * i;
            s = fmaf(sD[m * GP + g], g_weff[m], s);
            s = fmaf(sCt[g * 256 + m], g_weff[256 + m], s);
        }
        s = wredsum(s);
        if (lane == 0 && base + g < CB) out[base + g] = s + g_beff[0];
    }
    for (int p = tid; p < G * CT; p += 512) {
        int g = p >> 6, tt = p & 63;
        if (base + g < CB)
            out[CB + (size_t)(base + g) * CT + tt] = sL[g * 64 + tt];
    }
}

// ---------------- launcher ----------------
extern "C" void kernel_launch(void* const* d_in, const int* in_sizes, int n_in,
                              void* d_out, int out_size)
{
    (void)in_sizes; (void)n_in; (void)out_size;
    const float* enc = (const float*)d_in[0];
    const float* y   = (const float*)d_in[1];
    const float* Wd  = (const float*)d_in[2];
    const float* Wdb = (const float*)d_in[3];
    const float* Ud  = (const float*)d_in[4];
    const float* vd  = (const float*)d_in[5];
    const float* wt  = (const float*)d_in[6];
    const float* wtb = (const float*)d_in[7];
    const float* Wy  = (const float*)d_in[8];
    const float* Wyb = (const float*)d_in[9];
    const float* vy  = (const float*)d_in[10];
    const float* vyb = (const float*)d_in[11];
    const float* Wih = (const float*)d_in[12];
    const float* Whh = (const float*)d_in[13];
    const float* bih = (const float*)d_in[14];
    const float* bhh = (const float*)d_in[15];
    float* out = (float*)d_out;

    cudaFuncSetAttribute(decoder_kernel,
                         cudaFuncAttributeMaxDynamicSharedMemorySize, SMEM_BYTES);

    prep_kernel<<<455, 256>>>(Wd, Whh, Ud, bih, bhh, vy, Wy, Wyb, vyb);
    ue_kernel<<<8192, 256>>>(enc, wt);
    decoder_kernel<<<NBLK, 512, SMEM_BYTES>>>(y, Wdb, vd, wt, wtb, Wih, out);
}

// round 7
// speedup vs baseline: 6.0598x; 1.0380x over previous
#include <cuda_runtime.h>
#include <cuda_fp16.h>
#include <cstdint>

// Problem constants
#define CB   2048
#define CT   64
#define CM   256
#define CP   256
#define G    14
#define GP   20      // padded batch stride (floats)
#define NBLK 147
#define DSS  520     // sDSh row stride in halves ([d(256) | c(256)] + pad)

// smem layout (float offsets)
#define OFF_SGATE 0        // [1024][GP] fp32 gates        = 20480
#define OFF_SD    20480    // [256][GP] fp32 hidden d      = 5120
#define OFF_SS    25600    // [256][GP] fp32 cell c        = 5120
#define OFF_SDSH  30720    // [16][DSS] fp16 [d|c]         = 4160 floats
#define OFF_SX1H  34880    // [16][256] fp16 x1            = 2048 floats
#define OFF_SCT   36928    // [14][256] fp32 context       = 3584
#define OFF_SL    40512    // [14][64] scores/beta         = 896
#define OFF_SYT   41408    // [16] y_tilda
#define SMEM_FLOATS 41424
#define SMEM_BYTES  (SMEM_FLOATS * 4)

typedef unsigned long long ull;

// ---------------- device scratch ----------------
__device__ __align__(16) __half  g_UeH[(size_t)CB * CT * CM];   // fp16 Ue
__device__ __align__(16) __half  g_encH[(size_t)CB * CT * CM];  // fp16 enc
__device__ __align__(16) float   g_we[(size_t)CB * CT];         // enc . w_tilda
__device__ __align__(16) uint4   g_WdF[16 * 32 * 32];           // Wd  fragments [w][kt][lane]
__device__ __align__(16) uint4   g_WhhF[16 * 16 * 4 * 32];      // Whh fragments [w][kt][mt][lane]
__device__ __align__(16) float   g_UdT[256 * 256];
__device__ float g_bcomb[1024];
__device__ float g_weff[512];
__device__ float g_beff[1];

// ---------------- helpers ----------------
__device__ __forceinline__ ull pack2(float lo, float hi) {
    ull r; asm("mov.b64 %0, {%1, %2};" : "=l"(r) : "f"(lo), "f"(hi)); return r;
}
__device__ __forceinline__ ull bcast2(float x) { return pack2(x, x); }
__device__ __forceinline__ ull fma2(ull a, ull b, ull c) {
    ull d; asm("fma.rn.f32x2 %0, %1, %2, %3;" : "=l"(d) : "l"(a), "l"(b), "l"(c)); return d;
}
__device__ __forceinline__ float2 unpack2(ull v) {
    float2 f; asm("mov.b64 {%0, %1}, %2;" : "=f"(f.x), "=f"(f.y) : "l"(v)); return f;
}
__device__ __forceinline__ float fast_ex2(float x) {
    float y; asm("ex2.approx.f32 %0, %1;" : "=f"(y) : "f"(x)); return y;
}
__device__ __forceinline__ float fast_rcp(float x) {
    float y; asm("rcp.approx.f32 %0, %1;" : "=f"(y) : "f"(x)); return y;
}
__device__ __forceinline__ float tanh_f(float x) {
    float e = fast_ex2(2.8853900817779268f * x);
    return fmaf(-2.f, fast_rcp(e + 1.f), 1.f);
}
__device__ __forceinline__ unsigned tanh_h2(unsigned x) {
    unsigned y; asm("tanh.approx.f16x2 %0, %1;" : "=r"(y) : "r"(x)); return y;
}
__device__ __forceinline__ float sigm_f(float x) {
    float e = fast_ex2(-1.4426950408889634f * x);
    return fast_rcp(1.f + e);
}
__device__ __forceinline__ float wredsum(float s) {
#pragma unroll
    for (int o = 16; o; o >>= 1) s += __shfl_xor_sync(0xffffffffu, s, o);
    return s;
}
__device__ __forceinline__ float wredmax(float s) {
#pragma unroll
    for (int o = 16; o; o >>= 1) s = fmaxf(s, __shfl_xor_sync(0xffffffffu, s, o));
    return s;
}
// m16n8k16 row.col f32.f16.f16.f32
__device__ __forceinline__ void mma16816(float* c, uint4 A, uint32_t b0, uint32_t b1) {
    asm volatile("mma.sync.aligned.m16n8k16.row.col.f32.f16.f16.f32 "
        "{%0,%1,%2,%3}, {%4,%5,%6,%7}, {%8,%9}, {%0,%1,%2,%3};"
        : "+f"(c[0]), "+f"(c[1]), "+f"(c[2]), "+f"(c[3])
        : "r"(A.x), "r"(A.y), "r"(A.z), "r"(A.w), "r"(b0), "r"(b1));
}

// ---------------- prep: weight fragments + transposes + folded head ----------------
__global__ void prep_kernel(const float* __restrict__ Wd,
                            const float* __restrict__ Whh,
                            const float* __restrict__ Ud,
                            const float* __restrict__ bih,
                            const float* __restrict__ bhh,
                            const float* __restrict__ vy,
                            const float* __restrict__ Wy,
                            const float* __restrict__ Wyb,
                            const float* __restrict__ vyb)
{
    int i = blockIdx.x * blockDim.x + threadIdx.x;
    if (i < 16384) {   // Wd fragments: [w(16)][kt(32)][lane(32)]
        int lane = i & 31, kt = (i >> 5) & 31, w = i >> 10;
        int j0 = w * 16 + (lane >> 2);
        int k0 = kt * 16 + (lane & 3) * 2;
        __half2 a = __floats2half2_rn(Wd[j0 * 512 + k0],       Wd[j0 * 512 + k0 + 1]);
        __half2 b = __floats2half2_rn(Wd[(j0 + 8) * 512 + k0], Wd[(j0 + 8) * 512 + k0 + 1]);
        __half2 c = __floats2half2_rn(Wd[j0 * 512 + k0 + 8],   Wd[j0 * 512 + k0 + 9]);
        __half2 d = __floats2half2_rn(Wd[(j0 + 8) * 512 + k0 + 8], Wd[(j0 + 8) * 512 + k0 + 9]);
        uint4 v;
        v.x = *(uint32_t*)&a; v.y = *(uint32_t*)&b; v.z = *(uint32_t*)&c; v.w = *(uint32_t*)&d;
        g_WdF[i] = v;
        return;
    }
    i -= 16384;
    if (i < 32768) {   // Whh fragments: [w(16)][kt(16)][mt(4)][lane(32)]
        int lane = i & 31, mt = (i >> 5) & 3, kt = (i >> 7) & 15, w = i >> 11;
        int j0 = w * 64 + mt * 16 + (lane >> 2);
        int k0 = kt * 16 + (lane & 3) * 2;
        __half2 a = __floats2half2_rn(Whh[j0 * 256 + k0],       Whh[j0 * 256 + k0 + 1]);
        __half2 b = __floats2half2_rn(Whh[(j0 + 8) * 256 + k0], Whh[(j0 + 8) * 256 + k0 + 1]);
        __half2 c = __floats2half2_rn(Whh[j0 * 256 + k0 + 8],   Whh[j0 * 256 + k0 + 9]);
        __half2 d = __floats2half2_rn(Whh[(j0 + 8) * 256 + k0 + 8], Whh[(j0 + 8) * 256 + k0 + 9]);
        uint4 v;
        v.x = *(uint32_t*)&a; v.y = *(uint32_t*)&b; v.z = *(uint32_t*)&c; v.w = *(uint32_t*)&d;
        g_WhhF[i] = v;
        return;
    }
    i -= 32768;
    if (i < 65536) { int m = i >> 8, n = i & 255; g_UdT[i] = Ud[n * 256 + m]; return; }
    i -= 65536;
    if (i < 1024) { g_bcomb[i] = bih[i] + bhh[i]; return; }
    i -= 1024;
    if (i < 512) {
        float s = 0.f;
        for (int j = 0; j < 256; ++j) s += vy[j] * Wy[j * 512 + i];
        g_weff[i] = s; return;
    }
    i -= 512;
    if (i == 0) {
        float s = 0.f;
        for (int j = 0; j < 256; ++j) s += vy[j] * Wyb[j];
        g_beff[0] = s + vyb[0];
    }
}

// ---------------- Ue = enc @ U_d^T ; fp16 enc copy ; we = enc . w_tilda ----------------
__global__ __launch_bounds__(256) void ue_kernel(const float* __restrict__ enc,
                                                 const float* __restrict__ wt)
{
    __shared__ __align__(16) float Es[32][20];
    int bt0 = blockIdx.x * 16;
    int n = threadIdx.x;
    int lane = n & 31, wid = n >> 5;
    ull acc2[8];
#pragma unroll
    for (int j = 0; j < 8; ++j) acc2[j] = 0ull;

    for (int m0 = 0; m0 < 256; m0 += 32) {
        __syncthreads();
#pragma unroll
        for (int j = 0; j < 2; ++j) {
            int idx = n + j * 256;
            int r = idx >> 5, k = idx & 31;
            float v = enc[(size_t)(bt0 + r) * 256 + m0 + k];
            Es[k][r] = v;
            g_encH[(size_t)(bt0 + r) * 256 + m0 + k] = __float2half_rn(v);
        }
        __syncthreads();
#pragma unroll 8
        for (int k = 0; k < 32; ++k) {
            ull w2 = bcast2(g_UdT[(m0 + k) * 256 + n]);
            const ulonglong2* rp = (const ulonglong2*)&Es[k][0];
            ulonglong2 p0 = rp[0], p1 = rp[1], p2 = rp[2], p3 = rp[3];
            acc2[0] = fma2(w2, p0.x, acc2[0]);
            acc2[1] = fma2(w2, p0.y, acc2[1]);
            acc2[2] = fma2(w2, p1.x, acc2[2]);
            acc2[3] = fma2(w2, p1.y, acc2[3]);
            acc2[4] = fma2(w2, p2.x, acc2[4]);
            acc2[5] = fma2(w2, p2.y, acc2[5]);
            acc2[6] = fma2(w2, p3.x, acc2[6]);
            acc2[7] = fma2(w2, p3.y, acc2[7]);
        }
    }
#pragma unroll
    for (int j = 0; j < 8; ++j) {
        float2 f = unpack2(acc2[j]);
        g_UeH[(size_t)(bt0 + 2 * j)     * 256 + n] = __float2half_rn(f.x);
        g_UeH[(size_t)(bt0 + 2 * j + 1) * 256 + n] = __float2half_rn(f.y);
    }
    for (int r = wid; r < 16; r += 8) {
        const float* ep = enc + (size_t)(bt0 + r) * 256;
        float s = 0.f;
#pragma unroll
        for (int i = 0; i < 8; ++i) s = fmaf(ep[lane + 32 * i], wt[lane + 32 * i], s);
        s = wredsum(s);
        if (lane == 0) g_we[bt0 + r] = s;
    }
}

// ---------------- persistent decoder ----------------
__global__ __launch_bounds__(512, 1) void decoder_kernel(
    const float* __restrict__ yin,
    const float* __restrict__ Wdb, const float* __restrict__ vd,
    const float* __restrict__ wt,  const float* __restrict__ wtb,
    const float* __restrict__ Wih, float* __restrict__ out)
{
    extern __shared__ __align__(16) float sm[];
    float*  sGate = sm + OFF_SGATE;
    float*  sD    = sm + OFF_SD;
    float*  sS    = sm + OFF_SS;
    __half* sDSh  = (__half*)(sm + OFF_SDSH);
    __half* sX1h  = (__half*)(sm + OFF_SX1H);
    float*  sCt   = sm + OFF_SCT;
    float*  sL    = sm + OFF_SL;
    float*  sYt   = sm + OFF_SYT;

    const int tid  = threadIdx.x;
    const int lane = tid & 31;
    const int wid  = tid >> 5;
    const int half = tid >> 8;
    const int n    = tid & 255;
    const int base = blockIdx.x * G;

    // zero state: sD + sS (fp32) and sDSh (fp16) and sYt
    for (int i = tid; i < 10240; i += 512) sD[i] = 0.f;    // covers sD & sS
    for (int i = tid; i < 4160; i += 512) ((float*)sDSh)[i] = 0.f;
    if (tid < 16) sYt[tid] = 0.f;

    // cached per-lane vectors
    ull vd2[4];
#pragma unroll
    for (int j = 0; j < 4; ++j)
        vd2[j] = pack2(vd[lane * 8 + 2 * j], vd[lane * 8 + 2 * j + 1]);
    const float wt256 = wt[256];
    const float wtb0  = wtb[0];

    // per-thread pointwise constants (unit n)
    const float bI = g_bcomb[n],       wI = Wih[n];
    const float bF = g_bcomb[256 + n], wF = Wih[256 + n];
    const float bG = g_bcomb[512 + n], wG = Wih[512 + n];
    const float bO = g_bcomb[768 + n], wO = Wih[768 + n];

    // MMA geometry
    const int n0   = lane >> 2;          // B/C col within 8-tile
    const int koff = (lane & 3) * 2;
    const int r0A  = wid * 16 + n0;      // Phase-A output row
    const float bb0 = Wdb[r0A], bb1 = Wdb[r0A + 8];
    const uint4* afA = g_WdF  + (wid << 10) + lane;   // [w][kt][lane]
    const uint4* afE = g_WhhF + (wid << 11) + lane;   // [w][kt][mt][lane]

    __syncthreads();

    for (int t = 0; t < CT; ++t) {
        // ---- MMA-A: x1[256x16] = Wd[256x512] @ [d;c][512x16] ----
        {
            float c0[4] = {0, 0, 0, 0}, c1[4] = {0, 0, 0, 0};
#pragma unroll 4
            for (int kt = 0; kt < 32; ++kt) {
                uint4 A = afA[kt << 5];
                int k0 = (kt << 4) + koff;
                uint32_t b00 = *(const uint32_t*)(sDSh + n0 * DSS + k0);
                uint32_t b01 = *(const uint32_t*)(sDSh + n0 * DSS + k0 + 8);
                uint32_t b10 = *(const uint32_t*)(sDSh + (8 + n0) * DSS + k0);
                uint32_t b11 = *(const uint32_t*)(sDSh + (8 + n0) * DSS + k0 + 8);
                mma16816(c0, A, b00, b01);
                mma16816(c1, A, b10, b11);
            }
            int g0 = (lane & 3) * 2;
            sX1h[g0 * 256 + r0A]           = __float2half_rn(c0[0] + bb0);
            sX1h[(g0 + 1) * 256 + r0A]     = __float2half_rn(c0[1] + bb0);
            sX1h[g0 * 256 + r0A + 8]       = __float2half_rn(c0[2] + bb1);
            sX1h[(g0 + 1) * 256 + r0A + 8] = __float2half_rn(c0[3] + bb1);
            sX1h[(g0 + 8) * 256 + r0A]           = __float2half_rn(c1[0] + bb0);
            sX1h[(g0 + 9) * 256 + r0A]           = __float2half_rn(c1[1] + bb0);
            sX1h[(g0 + 8) * 256 + r0A + 8]       = __float2half_rn(c1[2] + bb1);
            sX1h[(g0 + 9) * 256 + r0A + 8]       = __float2half_rn(c1[3] + bb1);
        }
        __syncthreads();

        // ---- Phase B: attention scores (fp16, 4-way interleave, u-prefetch) ----
        // followed IMMEDIATELY (no barrier) by MMA-E so B's MUFU/LSU work and
        // E's HMMA work from drifting warps overlap across pipes.
        {
            uint4 u[4];
#pragma unroll
            for (int j = 0; j < 4; ++j) {
                int p = wid + 16 * j;
                int b = min(base + (p >> 6), CB - 1);
                u[j] = *((const uint4*)(g_UeH + (((size_t)b * CT + (p & 63)) << 8)) + lane);
            }
            for (int p0 = wid; p0 < G * CT; p0 += 64) {
                uint4 uc[4];
#pragma unroll
                for (int j = 0; j < 4; ++j) uc[j] = u[j];
                int pn = p0 + 64;
                if (pn < G * CT) {
#pragma unroll
                    for (int j = 0; j < 4; ++j) {
                        int p = pn + 16 * j;
                        int b = min(base + (p >> 6), CB - 1);
                        u[j] = *((const uint4*)(g_UeH + (((size_t)b * CT + (p & 63)) << 8)) + lane);
                    }
                }
                float sres[4];
#pragma unroll
                for (int j = 0; j < 4; ++j) {
                    int p = p0 + 16 * j;
                    uint4 x = *((const uint4*)(sX1h + ((p >> 6) << 8)) + lane);
                    const __half2* uh = (const __half2*)&uc[j];
                    const __half2* xh = (const __half2*)&x;
                    __half2 s0 = __hadd2(uh[0], xh[0]);
                    __half2 s1 = __hadd2(uh[1], xh[1]);
                    __half2 s2 = __hadd2(uh[2], xh[2]);
                    __half2 s3 = __hadd2(uh[3], xh[3]);
                    unsigned z0 = tanh_h2(*(unsigned*)&s0);
                    unsigned z1 = tanh_h2(*(unsigned*)&s1);
                    unsigned z2 = tanh_h2(*(unsigned*)&s2);
                    unsigned z3 = tanh_h2(*(unsigned*)&s3);
                    float2 f0 = __half22float2(*(__half2*)&z0);
                    float2 f1 = __half22float2(*(__half2*)&z1);
                    float2 f2 = __half22float2(*(__half2*)&z2);
                    float2 f3 = __half22float2(*(__half2*)&z3);
                    ull acc = 0ull;
                    acc = fma2(pack2(f0.x, f0.y), vd2[0], acc);
                    acc = fma2(pack2(f1.x, f1.y), vd2[1], acc);
                    acc = fma2(pack2(f2.x, f2.y), vd2[2], acc);
                    acc = fma2(pack2(f3.x, f3.y), vd2[3], acc);
                    float2 f = unpack2(acc);
                    sres[j] = f.x + f.y;
                }
#pragma unroll
                for (int o = 16; o; o >>= 1) {
#pragma unroll
                    for (int j = 0; j < 4; ++j)
                        sres[j] += __shfl_xor_sync(0xffffffffu, sres[j], o);
                }
                if (lane == 0) {
#pragma unroll
                    for (int j = 0; j < 4; ++j) sL[p0 + 16 * j] = sres[j];
                }
            }
        }

        // ---- MMA-E: gates[1024x16] = Whh[1024x256] @ d[256x16] (overlaps B across warps) ----
        {
            float c[4][2][4];
#pragma unroll
            for (int mt = 0; mt < 4; ++mt)
#pragma unroll
                for (int nt = 0; nt < 2; ++nt)
#pragma unroll
                    for (int q = 0; q < 4; ++q) c[mt][nt][q] = 0.f;
#pragma unroll 2
            for (int kt = 0; kt < 16; ++kt) {
                int k0 = (kt << 4) + koff;
                uint32_t b00 = *(const uint32_t*)(sDSh + n0 * DSS + k0);
                uint32_t b01 = *(const uint32_t*)(sDSh + n0 * DSS + k0 + 8);
                uint32_t b10 = *(const uint32_t*)(sDSh + (8 + n0) * DSS + k0);
                uint32_t b11 = *(const uint32_t*)(sDSh + (8 + n0) * DSS + k0 + 8);
#pragma unroll
                for (int mt = 0; mt < 4; ++mt) {
                    uint4 A = afE[((kt << 2) + mt) << 5];
                    mma16816(c[mt][0], A, b00, b01);
                    mma16816(c[mt][1], A, b10, b11);
                }
            }
            int g0 = (lane & 3) * 2;
#pragma unroll
            for (int mt = 0; mt < 4; ++mt) {
                int r = wid * 64 + mt * 16 + n0;
#pragma unroll
                for (int nt = 0; nt < 2; ++nt) {
                    int g = nt * 8 + g0;
                    *(float2*)&sGate[r * GP + g]       = make_float2(c[mt][nt][0], c[mt][nt][1]);
                    *(float2*)&sGate[(r + 8) * GP + g] = make_float2(c[mt][nt][2], c[mt][nt][3]);
                }
            }
        }
        __syncthreads();

        // ---- B2: softmax + fused y_tilda ----
        if (wid < G) {
            int g = wid;
            int b = min(base + g, CB - 1);
            float l0 = sL[g * 64 + lane], l1 = sL[g * 64 + 32 + lane];
            float mx = wredmax(fmaxf(l0, l1));
            float e0 = fast_ex2((l0 - mx) * 1.4426950408889634f);
            float e1 = fast_ex2((l1 - mx) * 1.4426950408889634f);
            float w0 = g_we[b * CT + lane], w1 = g_we[b * CT + 32 + lane];
            float ps = e0 + e1;
            float pw = fmaf(e0, w0, e1 * w1);
#pragma unroll
            for (int o = 16; o; o >>= 1) {
                ps += __shfl_xor_sync(0xffffffffu, ps, o);
                pw += __shfl_xor_sync(0xffffffffu, pw, o);
            }
            float inv = fast_rcp(ps);
            inv = inv * (2.f - ps * inv);
            sL[g * 64 + lane]      = e0 * inv;
            sL[g * 64 + 32 + lane] = e1 * inv;
            if (lane == 0) {
                float yt = yin[b * CT + t];
                sYt[g] = fmaf(pw, inv, fmaf(yt, wt256, wtb0));
            }
        }
        __syncthreads();

        // ---- E-final: LSTM pointwise (thread = unit n; half picks batch range) ----
        {
#pragma unroll
            for (int gi = 0; gi < 7; ++gi) {
                int g = half * 7 + gi;
                float yt = sYt[g];
                float iv = sGate[n * GP + g]         + bI + yt * wI;
                float fv = sGate[(256 + n) * GP + g] + bF + yt * wF;
                float gv = sGate[(512 + n) * GP + g] + bG + yt * wG;
                float ov = sGate[(768 + n) * GP + g] + bO + yt * wO;
                float c_old = sS[n * GP + g];
                float cn = fmaf(sigm_f(fv), c_old, sigm_f(iv) * tanh_f(gv));
                sS[n * GP + g] = cn;
                float h = sigm_f(ov) * tanh_f(cn);
                sD[n * GP + g] = h;
                sDSh[g * DSS + n]       = __float2half_rn(h);
                sDSh[g * DSS + 256 + n] = __float2half_rn(cn);
            }
        }
        __syncthreads();
    }

    // ---- Phase C (once): c_t = beta @ enc ----
    if (wid < G) {
        int g = wid;
        int b = min(base + g, CB - 1);
        const uint4* ep = (const uint4*)(g_encH + ((size_t)b * CT << 8)) + lane;
        ull a0 = 0ull, a1 = 0ull, a2 = 0ull, a3 = 0ull;
        for (int t0 = 0; t0 < 64; t0 += 8) {
            uint4 uu[8];
#pragma unroll
            for (int j = 0; j < 8; ++j) uu[j] = ep[(t0 + j) << 5];
#pragma unroll
            for (int j = 0; j < 8; ++j) {
                ull b2 = bcast2(sL[g * 64 + t0 + j]);
                const __half2* uh = (const __half2*)&uu[j];
                float2 e0 = __half22float2(uh[0]), e1 = __half22float2(uh[1]);
                float2 e2 = __half22float2(uh[2]), e3 = __half22float2(uh[3]);
                a0 = fma2(b2, pack2(e0.x, e0.y), a0);
                a1 = fma2(b2, pack2(e1.x, e1.y), a1);
                a2 = fma2(b2, pack2(e2.x, e2.y), a2);
                a3 = fma2(b2, pack2(e3.x, e3.y), a3);
            }
        }
        float* cp = sCt + g * 256 + lane * 8;
        float2 f0 = unpack2(a0), f1 = unpack2(a1);
        float2 f2 = unpack2(a2), f3 = unpack2(a3);
        ((float4*)cp)[0] = make_float4(f0.x, f0.y, f1.x, f1.y);
        ((float4*)cp)[1] = make_float4(f2.x, f2.y, f3.x, f3.y);
    }
    __syncthreads();

    // ---- Final head ----
    if (wid < G) {
        int g = wid;
        float s = 0.f;
#pragma unroll
        for (int i = 0; i < 8; ++i) {
            int m = lane + 32 * i;
            s = fmaf(sD[m * GP + g], g_weff[m], s);
            s = fmaf(sCt[g * 256 + m], g_weff[256 + m], s);
        }
        s = wredsum(s);
        if (lane == 0 && base + g < CB) out[base + g] = s + g_beff[0];
    }
    for (int p = tid; p < G * CT; p += 512) {
        int g = p >> 6, tt = p & 63;
        if (base + g < CB)
            out[CB + (size_t)(base + g) * CT + tt] = sL[g * 64 + tt];
    }
}

// ---------------- launcher ----------------
extern "C" void kernel_launch(void* const* d_in, const int* in_sizes, int n_in,
                              void* d_out, int out_size)
{
    (void)in_sizes; (void)n_in; (void)out_size;
    const float* enc = (const float*)d_in[0];
    const float* y   = (const float*)d_in[1];
    const float* Wd  = (const float*)d_in[2];
    const float* Wdb = (const float*)d_in[3];
    const float* Ud  = (const float*)d_in[4];
    const float* vd  = (const float*)d_in[5];
    const float* wt  = (const float*)d_in[6];
    const float* wtb = (const float*)d_in[7];
    const float* Wy  = (const float*)d_in[8];
    const float* Wyb = (const float*)d_in[9];
    const float* vy  = (const float*)d_in[10];
    const float* vyb = (const float*)d_in[11];
    const float* Wih = (const float*)d_in[12];
    const float* Whh = (const float*)d_in[13];
    const float* bih = (const float*)d_in[14];
    const float* bhh = (const float*)d_in[15];
    float* out = (float*)d_out;

    cudaFuncSetAttribute(decoder_kernel,
                         cudaFuncAttributeMaxDynamicSharedMemorySize, SMEM_BYTES);

    prep_kernel<<<455, 256>>>(Wd, Whh, Ud, bih, bhh, vy, Wy, Wyb, vyb);
    ue_kernel<<<8192, 256>>>(enc, wt);
    decoder_kernel<<<NBLK, 512, SMEM_BYTES>>>(y, Wdb, vd, wt, wtb, Wih, out);
}

// round 9
// speedup vs baseline: 7.9311x; 1.3088x over previous
#include <cuda_runtime.h>
#include <cuda_fp16.h>
#include <cstdint>

// Problem constants
#define CB   2048
#define CT   64
#define CM   256
#define CP   256
#define G    14
#define GP   20      // padded batch stride (floats)
#define NBLK 147
#define DSS  520     // sDSh row stride in halves ([d(256) | c(256)] + pad)

// decoder smem layout (float offsets)
#define OFF_SGATE 0        // [1024][GP] fp32 gates        = 20480
#define OFF_SD    20480    // [256][GP] fp32 hidden d      = 5120
#define OFF_SS    25600    // [256][GP] fp32 cell c        = 5120
#define OFF_SDSH  30720    // [16][DSS] fp16 [d|c]         = 4160 floats
#define OFF_SX1H  34880    // [16][256] fp16 x1            = 2048 floats
#define OFF_SCT   36928    // [14][256] fp32 context       = 3584
#define OFF_SL    40512    // [14][64] scores/beta         = 896
#define OFF_SYT   41408    // [16] y_tilda
#define SMEM_FLOATS 41424
#define SMEM_BYTES  (SMEM_FLOATS * 4)

// ue_tc smem: [128][280] halves
#define UE_STRIDE 280
#define UE_SMEM_BYTES (128 * UE_STRIDE * 2)

typedef unsigned long long ull;

// ---------------- device scratch ----------------
__device__ __align__(16) __half  g_UeH[(size_t)CB * CT * CM];   // fp16 Ue
__device__ __align__(16) __half  g_encH[(size_t)CB * CT * CM];  // fp16 enc
__device__ __align__(16) float   g_we[(size_t)CB * CT];         // enc . w_tilda
__device__ __align__(16) uint4   g_WdF[16 * 32 * 32];           // Wd  fragments [w][kt][lane]
__device__ __align__(16) uint4   g_WhhF[16 * 16 * 4 * 32];      // Whh fragments [w][kt][mt][lane]
__device__ __align__(16) uint2   g_UdF2[32 * 16 * 32];          // Ud  B-fragments [nt][kt][lane]
__device__ float g_bcomb[1024];
__device__ float g_weff[512];
__device__ float g_beff[1];

// ---------------- helpers ----------------
__device__ __forceinline__ ull pack2(float lo, float hi) {
    ull r; asm("mov.b64 %0, {%1, %2};" : "=l"(r) : "f"(lo), "f"(hi)); return r;
}
__device__ __forceinline__ ull bcast2(float x) { return pack2(x, x); }
__device__ __forceinline__ ull fma2(ull a, ull b, ull c) {
    ull d; asm("fma.rn.f32x2 %0, %1, %2, %3;" : "=l"(d) : "l"(a), "l"(b), "l"(c)); return d;
}
__device__ __forceinline__ float2 unpack2(ull v) {
    float2 f; asm("mov.b64 {%0, %1}, %2;" : "=f"(f.x), "=f"(f.y) : "l"(v)); return f;
}
__device__ __forceinline__ float fast_ex2(float x) {
    float y; asm("ex2.approx.f32 %0, %1;" : "=f"(y) : "f"(x)); return y;
}
__device__ __forceinline__ float fast_rcp(float x) {
    float y; asm("rcp.approx.f32 %0, %1;" : "=f"(y) : "f"(x)); return y;
}
__device__ __forceinline__ float tanh_f(float x) {
    float e = fast_ex2(2.8853900817779268f * x);
    return fmaf(-2.f, fast_rcp(e + 1.f), 1.f);
}
__device__ __forceinline__ unsigned tanh_h2(unsigned x) {
    unsigned y; asm("tanh.approx.f16x2 %0, %1;" : "=r"(y) : "r"(x)); return y;
}
__device__ __forceinline__ float sigm_f(float x) {
    float e = fast_ex2(-1.4426950408889634f * x);
    return fast_rcp(1.f + e);
}
__device__ __forceinline__ float wredsum(float s) {
#pragma unroll
    for (int o = 16; o; o >>= 1) s += __shfl_xor_sync(0xffffffffu, s, o);
    return s;
}
__device__ __forceinline__ float wredmax(float s) {
#pragma unroll
    for (int o = 16; o; o >>= 1) s = fmaxf(s, __shfl_xor_sync(0xffffffffu, s, o));
    return s;
}
// m16n8k16 row.col f32.f16.f16.f32
__device__ __forceinline__ void mma16816(float* c, uint4 A, uint32_t b0, uint32_t b1) {
    asm volatile("mma.sync.aligned.m16n8k16.row.col.f32.f16.f16.f32 "
        "{%0,%1,%2,%3}, {%4,%5,%6,%7}, {%8,%9}, {%0,%1,%2,%3};"
        : "+f"(c[0]), "+f"(c[1]), "+f"(c[2]), "+f"(c[3])
        : "r"(A.x), "r"(A.y), "r"(A.z), "r"(A.w), "r"(b0), "r"(b1));
}

// ---------------- prep: weight fragments + folded head ----------------
__global__ void prep_kernel(const float* __restrict__ Wd,
                            const float* __restrict__ Whh,
                            const float* __restrict__ Ud,
                            const float* __restrict__ bih,
                            const float* __restrict__ bhh,
                            const float* __restrict__ vy,
                            const float* __restrict__ Wy,
                            const float* __restrict__ Wyb,
                            const float* __restrict__ vyb)
{
    int i = blockIdx.x * blockDim.x + threadIdx.x;
    if (i < 16384) {   // Wd fragments: [w(16)][kt(32)][lane(32)]
        int lane = i & 31, kt = (i >> 5) & 31, w = i >> 10;
        int j0 = w * 16 + (lane >> 2);
        int k0 = kt * 16 + (lane & 3) * 2;
        __half2 a = __floats2half2_rn(Wd[j0 * 512 + k0],       Wd[j0 * 512 + k0 + 1]);
        __half2 b = __floats2half2_rn(Wd[(j0 + 8) * 512 + k0], Wd[(j0 + 8) * 512 + k0 + 1]);
        __half2 c = __floats2half2_rn(Wd[j0 * 512 + k0 + 8],   Wd[j0 * 512 + k0 + 9]);
        __half2 d = __floats2half2_rn(Wd[(j0 + 8) * 512 + k0 + 8], Wd[(j0 + 8) * 512 + k0 + 9]);
        uint4 v;
        v.x = *(uint32_t*)&a; v.y = *(uint32_t*)&b; v.z = *(uint32_t*)&c; v.w = *(uint32_t*)&d;
        g_WdF[i] = v;
        return;
    }
    i -= 16384;
    if (i < 32768) {   // Whh fragments: [w(16)][kt(16)][mt(4)][lane(32)]
        int lane = i & 31, mt = (i >> 5) & 3, kt = (i >> 7) & 15, w = i >> 11;
        int j0 = w * 64 + mt * 16 + (lane >> 2);
        int k0 = kt * 16 + (lane & 3) * 2;
        __half2 a = __floats2half2_rn(Whh[j0 * 256 + k0],       Whh[j0 * 256 + k0 + 1]);
        __half2 b = __floats2half2_rn(Whh[(j0 + 8) * 256 + k0], Whh[(j0 + 8) * 256 + k0 + 1]);
        __half2 c = __floats2half2_rn(Whh[j0 * 256 + k0 + 8],   Whh[j0 * 256 + k0 + 9]);
        __half2 d = __floats2half2_rn(Whh[(j0 + 8) * 256 + k0 + 8], Whh[(j0 + 8) * 256 + k0 + 9]);
        uint4 v;
        v.x = *(uint32_t*)&a; v.y = *(uint32_t*)&b; v.z = *(uint32_t*)&c; v.w = *(uint32_t*)&d;
        g_WhhF[i] = v;
        return;
    }
    i -= 32768;
    if (i < 16384) {   // Ud B-fragments: [nt(32)][kt(16)][lane(32)]
        int lane = i & 31, kt = (i >> 5) & 15, nt = i >> 9;
        int n = nt * 8 + (lane >> 2);
        int k0 = kt * 16 + (lane & 3) * 2;
        __half2 b0 = __floats2half2_rn(Ud[n * 256 + k0],     Ud[n * 256 + k0 + 1]);
        __half2 b1 = __floats2half2_rn(Ud[n * 256 + k0 + 8], Ud[n * 256 + k0 + 9]);
        uint2 v; v.x = *(uint32_t*)&b0; v.y = *(uint32_t*)&b1;
        g_UdF2[i] = v;
        return;
    }
    i -= 16384;
    if (i < 1024) { g_bcomb[i] = bih[i] + bhh[i]; return; }
    i -= 1024;
    if (i < 512) {
        float s = 0.f;
        for (int j = 0; j < 256; ++j) s += vy[j] * Wy[j * 512 + i];
        g_weff[i] = s; return;
    }
    i -= 512;
    if (i == 0) {
        float s = 0.f;
        for (int j = 0; j < 256; ++j) s += vy[j] * Wyb[j];
        g_beff[0] = s + vyb[0];
    }
}

// ---------------- ue_tc: Ue = enc @ Ud^T via HMMA; encH copy; we = enc.wt ----------------
__global__ __launch_bounds__(256, 2) void ue_tc_kernel(const float* __restrict__ enc,
                                                       const float* __restrict__ wt)
{
    extern __shared__ __align__(16) __half Eh[];   // [128][UE_STRIDE]
    const int tid  = threadIdx.x;
    const int lane = tid & 31;
    const int w    = tid >> 5;
    const int bt0  = blockIdx.x * 128;

    // load enc fp32 -> fp16: smem + g_encH (vectorized)
    for (int i = tid; i < 8192; i += 256) {
        int r = i >> 6, c4 = i & 63;
        float4 v = ((const float4*)(enc + (size_t)(bt0 + r) * 256))[c4];
        __half2 h0 = __floats2half2_rn(v.x, v.y);
        __half2 h1 = __floats2half2_rn(v.z, v.w);
        *(__half2*)&Eh[r * UE_STRIDE + c4 * 4]     = h0;
        *(__half2*)&Eh[r * UE_STRIDE + c4 * 4 + 2] = h1;
        uint2 pk; pk.x = *(uint32_t*)&h0; pk.y = *(uint32_t*)&h1;
        *(uint2*)(g_encH + (size_t)(bt0 + r) * 256 + c4 * 4) = pk;
    }
    __syncthreads();

    // we[bt] = enc . wt  (fp32 accum over fp16 enc)
    {
        float2 wtr[4];
#pragma unroll
        for (int i = 0; i < 4; ++i)
            wtr[i] = make_float2(wt[i * 64 + lane * 2], wt[i * 64 + lane * 2 + 1]);
        for (int r = w; r < 128; r += 8) {
            float s = 0.f;
#pragma unroll
            for (int i = 0; i < 4; ++i) {
                float2 f = __half22float2(*(__half2*)&Eh[r * UE_STRIDE + i * 64 + lane * 2]);
                s = fmaf(f.x, wtr[i].x, fmaf(f.y, wtr[i].y, s));
            }
            s = wredsum(s);
            if (lane == 0) g_we[bt0 + r] = s;
        }
    }

    // HMMA: warp w -> rows [w*16, w*16+16); two passes of 128 cols
    const int r0   = w * 16 + (lane >> 2);
    const int koff = (lane & 3) * 2;
    const int cc   = (lane & 3) * 2;
#pragma unroll
    for (int pass = 0; pass < 2; ++pass) {
        float acc[16][4];
#pragma unroll
        for (int nt = 0; nt < 16; ++nt)
#pragma unroll
            for (int q = 0; q < 4; ++q) acc[nt][q] = 0.f;

        for (int kt = 0; kt < 16; ++kt) {
            uint4 A;
            A.x = *(const uint32_t*)&Eh[r0 * UE_STRIDE + kt * 16 + koff];
            A.y = *(const uint32_t*)&Eh[(r0 + 8) * UE_STRIDE + kt * 16 + koff];
            A.z = *(const uint32_t*)&Eh[r0 * UE_STRIDE + kt * 16 + koff + 8];
            A.w = *(const uint32_t*)&Eh[(r0 + 8) * UE_STRIDE + kt * 16 + koff + 8];
#pragma unroll
            for (int nt = 0; nt < 16; ++nt) {
                uint2 B = g_UdF2[((((pass * 16 + nt) << 4) + kt) << 5) + lane];
                mma16816(acc[nt], A, B.x, B.y);
            }
        }
#pragma unroll
        for (int nt = 0; nt < 16; ++nt) {
            int ncol = ((pass * 16 + nt) << 3) + cc;
            __half2 h01 = __floats2half2_rn(acc[nt][0], acc[nt][1]);
            __half2 h23 = __floats2half2_rn(acc[nt][2], acc[nt][3]);
            *(__half2*)(g_UeH + (size_t)(bt0 + r0) * 256 + ncol)     = h01;
            *(__half2*)(g_UeH + (size_t)(bt0 + r0 + 8) * 256 + ncol) = h23;
        }
    }
}

// ---------------- persistent decoder ----------------
__global__ __launch_bounds__(512, 1) void decoder_kernel(
    const float* __restrict__ yin,
    const float* __restrict__ Wdb, const float* __restrict__ vd,
    const float* __restrict__ wt,  const float* __restrict__ wtb,
    const float* __restrict__ Wih, float* __restrict__ out)
{
    extern __shared__ __align__(16) float sm[];
    float*  sGate = sm + OFF_SGATE;
    float*  sD    = sm + OFF_SD;
    float*  sS    = sm + OFF_SS;
    __half* sDSh  = (__half*)(sm + OFF_SDSH);
    __half* sX1h  = (__half*)(sm + OFF_SX1H);
    float*  sCt   = sm + OFF_SCT;
    float*  sL    = sm + OFF_SL;
    float*  sYt   = sm + OFF_SYT;

    const int tid  = threadIdx.x;
    const int lane = tid & 31;
    const int wid  = tid >> 5;
    const int half = tid >> 8;
    const int n    = tid & 255;
    const int base = blockIdx.x * G;

    for (int i = tid; i < 10240; i += 512) sD[i] = 0.f;    // covers sD & sS
    for (int i = tid; i < 4160; i += 512) ((float*)sDSh)[i] = 0.f;
    if (tid < 16) sYt[tid] = 0.f;

    ull vd2[4];
#pragma unroll
    for (int j = 0; j < 4; ++j)
        vd2[j] = pack2(vd[lane * 8 + 2 * j], vd[lane * 8 + 2 * j + 1]);
    const float wt256 = wt[256];
    const float wtb0  = wtb[0];

    const float bI = g_bcomb[n],       wI = Wih[n];
    const float bF = g_bcomb[256 + n], wF = Wih[256 + n];
    const float bG = g_bcomb[512 + n], wG = Wih[512 + n];
    const float bO = g_bcomb[768 + n], wO = Wih[768 + n];

    const int n0   = lane >> 2;
    const int koff = (lane & 3) * 2;
    const int r0A  = wid * 16 + n0;
    const float bb0 = Wdb[r0A], bb1 = Wdb[r0A + 8];
    const uint4* afA = g_WdF  + (wid << 10) + lane;
    const uint4* afE = g_WhhF + (wid << 11) + lane;

    __syncthreads();

    for (int t = 0; t < CT; ++t) {
        // ---- MMA-A ----
        {
            float c0[4] = {0, 0, 0, 0}, c1[4] = {0, 0, 0, 0};
#pragma unroll 4
            for (int kt = 0; kt < 32; ++kt) {
                uint4 A = afA[kt << 5];
                int k0 = (kt << 4) + koff;
                uint32_t b00 = *(const uint32_t*)(sDSh + n0 * DSS + k0);
                uint32_t b01 = *(const uint32_t*)(sDSh + n0 * DSS + k0 + 8);
                uint32_t b10 = *(const uint32_t*)(sDSh + (8 + n0) * DSS + k0);
                uint32_t b11 = *(const uint32_t*)(sDSh + (8 + n0) * DSS + k0 + 8);
                mma16816(c0, A, b00, b01);
                mma16816(c1, A, b10, b11);
            }
            int g0 = (lane & 3) * 2;
            sX1h[g0 * 256 + r0A]           = __float2half_rn(c0[0] + bb0);
            sX1h[(g0 + 1) * 256 + r0A]     = __float2half_rn(c0[1] + bb0);
            sX1h[g0 * 256 + r0A + 8]       = __float2half_rn(c0[2] + bb1);
            sX1h[(g0 + 1) * 256 + r0A + 8] = __float2half_rn(c0[3] + bb1);
            sX1h[(g0 + 8) * 256 + r0A]           = __float2half_rn(c1[0] + bb0);
            sX1h[(g0 + 9) * 256 + r0A]           = __float2half_rn(c1[1] + bb0);
            sX1h[(g0 + 8) * 256 + r0A + 8]       = __float2half_rn(c1[2] + bb1);
            sX1h[(g0 + 9) * 256 + r0A + 8]       = __float2half_rn(c1[3] + bb1);
        }
        __syncthreads();

        // ---- Phase B (no barrier into MMA-E) ----
        {
            uint4 u[4];
#pragma unroll
            for (int j = 0; j < 4; ++j) {
                int p = wid + 16 * j;
                int b = min(base + (p >> 6), CB - 1);
                u[j] = *((const uint4*)(g_UeH + (((size_t)b * CT + (p & 63)) << 8)) + lane);
            }
            for (int p0 = wid; p0 < G * CT; p0 += 64) {
                uint4 uc[4];
#pragma unroll
                for (int j = 0; j < 4; ++j) uc[j] = u[j];
                int pn = p0 + 64;
                if (pn < G * CT) {
#pragma unroll
                    for (int j = 0; j < 4; ++j) {
                        int p = pn + 16 * j;
                        int b = min(base + (p >> 6), CB - 1);
                        u[j] = *((const uint4*)(g_UeH + (((size_t)b * CT + (p & 63)) << 8)) + lane);
                    }
                }
                float sres[4];
#pragma unroll
                for (int j = 0; j < 4; ++j) {
                    int p = p0 + 16 * j;
                    uint4 x = *((const uint4*)(sX1h + ((p >> 6) << 8)) + lane);
                    const __half2* uh = (const __half2*)&uc[j];
                    const __half2* xh = (const __half2*)&x;
                    __half2 s0 = __hadd2(uh[0], xh[0]);
                    __half2 s1 = __hadd2(uh[1], xh[1]);
                    __half2 s2 = __hadd2(uh[2], xh[2]);
                    __half2 s3 = __hadd2(uh[3], xh[3]);
                    unsigned z0 = tanh_h2(*(unsigned*)&s0);
                    unsigned z1 = tanh_h2(*(unsigned*)&s1);
                    unsigned z2 = tanh_h2(*(unsigned*)&s2);
                    unsigned z3 = tanh_h2(*(unsigned*)&s3);
                    float2 f0 = __half22float2(*(__half2*)&z0);
                    float2 f1 = __half22float2(*(__half2*)&z1);
                    float2 f2 = __half22float2(*(__half2*)&z2);
                    float2 f3 = __half22float2(*(__half2*)&z3);
                    ull acc = 0ull;
                    acc = fma2(pack2(f0.x, f0.y), vd2[0], acc);
                    acc = fma2(pack2(f1.x, f1.y), vd2[1], acc);
                    acc = fma2(pack2(f2.x, f2.y), vd2[2], acc);
                    acc = fma2(pack2(f3.x, f3.y), vd2[3], acc);
                    float2 f = unpack2(acc);
                    sres[j] = f.x + f.y;
                }
#pragma unroll
                for (int o = 16; o; o >>= 1) {
#pragma unroll
                    for (int j = 0; j < 4; ++j)
                        sres[j] += __shfl_xor_sync(0xffffffffu, sres[j], o);
                }
                if (lane == 0) {
#pragma unroll
                    for (int j = 0; j < 4; ++j) sL[p0 + 16 * j] = sres[j];
                }
            }
        }

        // ---- MMA-E ----
        {
            float c[4][2][4];
#pragma unroll
            for (int mt = 0; mt < 4; ++mt)
#pragma unroll
                for (int nt = 0; nt < 2; ++nt)
#pragma unroll
                    for (int q = 0; q < 4; ++q) c[mt][nt][q] = 0.f;
#pragma unroll 2
            for (int kt = 0; kt < 16; ++kt) {
                int k0 = (kt << 4) + koff;
                uint32_t b00 = *(const uint32_t*)(sDSh + n0 * DSS + k0);
                uint32_t b01 = *(const uint32_t*)(sDSh + n0 * DSS + k0 + 8);
                uint32_t b10 = *(const uint32_t*)(sDSh + (8 + n0) * DSS + k0);
                uint32_t b11 = *(const uint32_t*)(sDSh + (8 + n0) * DSS + k0 + 8);
#pragma unroll
                for (int mt = 0; mt < 4; ++mt) {
                    uint4 A = afE[((kt << 2) + mt) << 5];
                    mma16816(c[mt][0], A, b00, b01);
                    mma16816(c[mt][1], A, b10, b11);
                }
            }
            int g0 = (lane & 3) * 2;
#pragma unroll
            for (int mt = 0; mt < 4; ++mt) {
                int r = wid * 64 + mt * 16 + n0;
#pragma unroll
                for (int nt = 0; nt < 2; ++nt) {
                    int g = nt * 8 + g0;
                    *(float2*)&sGate[r * GP + g]       = make_float2(c[mt][nt][0], c[mt][nt][1]);
                    *(float2*)&sGate[(r + 8) * GP + g] = make_float2(c[mt][nt][2], c[mt][nt][3]);
                }
            }
        }
        __syncthreads();

        // ---- B2: softmax + fused y_tilda ----
        if (wid < G) {
            int g = wid;
            int b = min(base + g, CB - 1);
            float l0 = sL[g * 64 + lane], l1 = sL[g * 64 + 32 + lane];
            float mx = wredmax(fmaxf(l0, l1));
            float e0 = fast_ex2((l0 - mx) * 1.4426950408889634f);
            float e1 = fast_ex2((l1 - mx) * 1.4426950408889634f);
            float w0 = g_we[b * CT + lane], w1 = g_we[b * CT + 32 + lane];
            float ps = e0 + e1;
            float pw = fmaf(e0, w0, e1 * w1);
#pragma unroll
            for (int o = 16; o; o >>= 1) {
                ps += __shfl_xor_sync(0xffffffffu, ps, o);
                pw += __shfl_xor_sync(0xffffffffu, pw, o);
            }
            float inv = fast_rcp(ps);
            inv = inv * (2.f - ps * inv);
            sL[g * 64 + lane]      = e0 * inv;
            sL[g * 64 + 32 + lane] = e1 * inv;
            if (lane == 0) {
                float yt = yin[b * CT + t];
                sYt[g] = fmaf(pw, inv, fmaf(yt, wt256, wtb0));
            }
        }
        __syncthreads();

        // ---- E-final: LSTM pointwise ----
        {
#pragma unroll
            for (int gi = 0; gi < 7; ++gi) {
                int g = half * 7 + gi;
                float yt = sYt[g];
                float iv = sGate[n * GP + g]         + bI + yt * wI;
                float fv = sGate[(256 + n) * GP + g] + bF + yt * wF;
                float gv = sGate[(512 + n) * GP + g] + bG + yt * wG;
                float ov = sGate[(768 + n) * GP + g] + bO + yt * wO;
                float c_old = sS[n * GP + g];
                float cn = fmaf(sigm_f(fv), c_old, sigm_f(iv) * tanh_f(gv));
                sS[n * GP + g] = cn;
                float h = sigm_f(ov) * tanh_f(cn);
                sD[n * GP + g] = h;
                sDSh[g * DSS + n]       = __float2half_rn(h);
                sDSh[g * DSS + 256 + n] = __float2half_rn(cn);
            }
        }
        __syncthreads();
    }

    // ---- Phase C (once) ----
    if (wid < G) {
        int g = wid;
        int b = min(base + g, CB - 1);
        const uint4* ep = (const uint4*)(g_encH + ((size_t)b * CT << 8)) + lane;
        ull a0 = 0ull, a1 = 0ull, a2 = 0ull, a3 = 0ull;
        for (int t0 = 0; t0 < 64; t0 += 8) {
            uint4 uu[8];
#pragma unroll
            for (int j = 0; j < 8; ++j) uu[j] = ep[(t0 + j) << 5];
#pragma unroll
            for (int j = 0; j < 8; ++j) {
                ull b2 = bcast2(sL[g * 64 + t0 + j]);
                const __half2* uh = (const __half2*)&uu[j];
                float2 e0 = __half22float2(uh[0]), e1 = __half22float2(uh[1]);
                float2 e2 = __half22float2(uh[2]), e3 = __half22float2(uh[3]);
                a0 = fma2(b2, pack2(e0.x, e0.y), a0);
                a1 = fma2(b2, pack2(e1.x, e1.y), a1);
                a2 = fma2(b2, pack2(e2.x, e2.y), a2);
                a3 = fma2(b2, pack2(e3.x, e3.y), a3);
            }
        }
        float* cp = sCt + g * 256 + lane * 8;
        float2 f0 = unpack2(a0), f1 = unpack2(a1);
        float2 f2 = unpack2(a2), f3 = unpack2(a3);
        ((float4*)cp)[0] = make_float4(f0.x, f0.y, f1.x, f1.y);
        ((float4*)cp)[1] = make_float4(f2.x, f2.y, f3.x, f3.y);
    }
    __syncthreads();

    // ---- Final head ----
    if (wid < G) {
        int g = wid;
        float s = 0.f;
#pragma unroll
        for (int i = 0; i < 8; ++i) {
            int m = lane + 32 * i;
            s = fmaf(sD[m * GP + g], g_weff[m], s);
            s = fmaf(sCt[g * 256 + m], g_weff[256 + m], s);
        }
        s = wredsum(s);
        if (lane == 0 && base + g < CB) out[base + g] = s + g_beff[0];
    }
    for (int p = tid; p < G * CT; p += 512) {
        int g = p >> 6, tt = p & 63;
        if (base + g < CB)
            out[CB + (size_t)(base + g) * CT + tt] = sL[g * 64 + tt];
    }
}

// ---------------- launcher ----------------
extern "C" void kernel_launch(void* const* d_in, const int* in_sizes, int n_in,
                              void* d_out, int out_size)
{
    (void)in_sizes; (void)n_in; (void)out_size;
    const float* enc = (const float*)d_in[0];
    const float* y   = (const float*)d_in[1];
    const float* Wd  = (const float*)d_in[2];
    const float* Wdb = (const float*)d_in[3];
    const float* Ud  = (const float*)d_in[4];
    const float* vd  = (const float*)d_in[5];
    const float* wt  = (const float*)d_in[6];
    const float* wtb = (const float*)d_in[7];
    const float* Wy  = (const float*)d_in[8];
    const float* Wyb = (const float*)d_in[9];
    const float* vy  = (const float*)d_in[10];
    const float* vyb = (const float*)d_in[11];
    const float* Wih = (const float*)d_in[12];
    const float* Whh = (const float*)d_in[13];
    const float* bih = (const float*)d_in[14];
    const float* bhh = (const float*)d_in[15];
    float* out = (float*)d_out;

    cudaFuncSetAttribute(decoder_kernel,
                         cudaFuncAttributeMaxDynamicSharedMemorySize, SMEM_BYTES);
    cudaFuncSetAttribute(ue_tc_kernel,
                         cudaFuncAttributeMaxDynamicSharedMemorySize, UE_SMEM_BYTES);

    // 16384 + 32768 + 16384 + 1024 + 512 + 1 = 67073 threads -> 263 blocks of 256
    prep_kernel<<<263, 256>>>(Wd, Whh, Ud, bih, bhh, vy, Wy, Wyb, vyb);
    ue_tc_kernel<<<1024, 256, UE_SMEM_BYTES>>>(enc, wt);
    decoder_kernel<<<NBLK, 512, SMEM_BYTES>>>(y, Wdb, vd, wt, wtb, Wih, out);
}